// round 12
// baseline (speedup 1.0000x reference)
#include <cuda_runtime.h>
#include <cuda_fp16.h>
#include <cstdint>

// ---------------- problem constants ----------------
namespace {
constexpr int kB   = 8;
constexpr int kC   = 256;
constexpr int kN   = 4096;
constexpr int kC3  = 768;
constexpr int kFFN = 2048;
constexpr int kBH  = 32;
constexpr int kNCH = 16;     // 16 split-K CTAs per bh; pairs share one 512-n chunk

constexpr int ROWB   = 144;
constexpr int TILEB  = 128 * ROWB;
constexpr int STAGEB = 2 * TILEB;
constexpr int NSTG   = 3;
constexpr uint32_t SMEM_DYN = STAGEB * NSTG; // 110592 (2 CTAs/SM)

constexpr int OW_QKV  = 0;
constexpr int OW_PROJ = OW_QKV + kC3 * kC;
constexpr int OW_FFN1 = OW_PROJ + kC * kC;
constexpr int OW_FFN2 = OW_FFN1 + kFFN * kC;
constexpr int OW_TOT  = OW_FFN2 + kC * kFFN;
}

// ---------------- scratch ----------------
__device__ __half h_xln[kB * kN * kC];
// chunked q/k layout: [blk(64)][ch(8)][d(64)][nl(512)], blk=(qk*8+b)*4+h
__device__ __half h_qkT[4096 * 4096];
__device__ __half h_v[kB * kN * kC];
__device__ float  g_spart[kBH * kNCH * 64 * 64];
__device__ __half h_attnw[kBH * 64 * 64];
__device__ __half h_attnout[kB * kN * kC];
__device__ __half h_proj[kB * kN * kC];
__device__ __half h_ln2[kB * kN * kC];
__device__ __half h_ffh[kB * kN * kFFN];
__device__ __half h_w[OW_TOT];

// ---------------- helpers ----------------
__device__ __forceinline__ uint32_t smem_u32(const void* p) {
    uint32_t a;
    asm("{ .reg .u64 t; cvta.to.shared.u64 t, %1; cvt.u32.u64 %0, t; }" : "=r"(a) : "l"(p));
    return a;
}
__device__ __forceinline__ void cp_async16(uint32_t s, const void* g) {
    asm volatile("cp.async.cg.shared.global [%0], [%1], 16;" :: "r"(s), "l"(g));
}
#define CP_COMMIT() asm volatile("cp.async.commit_group;" ::: "memory")
#define CP_WAIT1()  asm volatile("cp.async.wait_group 1;" ::: "memory")
#define CP_WAIT0()  asm volatile("cp.async.wait_group 0;" ::: "memory")

__device__ __forceinline__ void ldsm4(uint32_t* r, uint32_t a) {
    asm volatile("ldmatrix.sync.aligned.m8n8.x4.shared.b16 {%0,%1,%2,%3}, [%4];"
                 : "=r"(r[0]), "=r"(r[1]), "=r"(r[2]), "=r"(r[3]) : "r"(a));
}
__device__ __forceinline__ void stsm4(uint32_t a, const uint32_t* r) {
    asm volatile("stmatrix.sync.aligned.m8n8.x4.shared.b16 [%0], {%1,%2,%3,%4};"
                 :: "r"(a), "r"(r[0]), "r"(r[1]), "r"(r[2]), "r"(r[3]) : "memory");
}
__device__ __forceinline__ void mma_f16(float* c,
                                        uint32_t a0, uint32_t a1, uint32_t a2, uint32_t a3,
                                        uint32_t b0, uint32_t b1) {
    asm volatile(
        "mma.sync.aligned.m16n8k16.row.col.f32.f16.f16.f32 "
        "{%0,%1,%2,%3}, {%4,%5,%6,%7}, {%8,%9}, {%0,%1,%2,%3};"
        : "+f"(c[0]), "+f"(c[1]), "+f"(c[2]), "+f"(c[3])
        : "r"(a0), "r"(a1), "r"(a2), "r"(a3), "r"(b0), "r"(b1));
}
__device__ __forceinline__ uint32_t pack_h2(float x, float y) {
    __half2 h = __floats2half2_rn(x, y);
    return *(uint32_t*)&h;
}

// ---------------- weight conversion ----------------
__global__ __launch_bounds__(256) void convw_kernel(const float* __restrict__ wqkv,
                                                    const float* __restrict__ wproj,
                                                    const float* __restrict__ wffn1,
                                                    const float* __restrict__ wffn2)
{
    int i = blockIdx.x * 256 + threadIdx.x;
    if (i >= OW_TOT) return;
    float v;
    if (i < OW_PROJ)       v = wqkv[i - OW_QKV];
    else if (i < OW_FFN1)  v = wproj[i - OW_PROJ];
    else if (i < OW_FFN2)  v = wffn1[i - OW_FFN1];
    else                   v = wffn2[i - OW_FFN2];
    h_w[i] = __float2half(v);
}

// ---------------- LN1 ----------------
__global__ __launch_bounds__(256) void ln1_kernel(const float* __restrict__ x,
                                                  const float* __restrict__ g1,
                                                  const float* __restrict__ be1)
{
    __shared__ float s[32][257];
    __shared__ float smu[32], srs[32];
    int b  = blockIdx.y;
    int n0 = blockIdx.x * 32;
    int tid = threadIdx.x;
    const float* xb = x + (size_t)b * kC * kN;
    #pragma unroll
    for (int it = 0; it < 32; ++it) {
        int idx = it * 256 + tid;
        int c = idx >> 5, nn = idx & 31;
        s[nn][c] = xb[(size_t)c * kN + n0 + nn];
    }
    __syncthreads();
    int nn = tid >> 3, g = tid & 7;
    float sum = 0.f, sq = 0.f;
    #pragma unroll
    for (int j = 0; j < 32; ++j) { float v = s[nn][g + j * 8]; sum += v; sq += v * v; }
    sum += __shfl_xor_sync(0xffffffffu, sum, 1, 8);
    sum += __shfl_xor_sync(0xffffffffu, sum, 2, 8);
    sum += __shfl_xor_sync(0xffffffffu, sum, 4, 8);
    sq  += __shfl_xor_sync(0xffffffffu, sq, 1, 8);
    sq  += __shfl_xor_sync(0xffffffffu, sq, 2, 8);
    sq  += __shfl_xor_sync(0xffffffffu, sq, 4, 8);
    if (g == 0) {
        float mu = sum * (1.f / 256.f);
        smu[nn] = mu;
        srs[nn] = rsqrtf(sq * (1.f / 256.f) - mu * mu + 1e-5f);
    }
    __syncthreads();
    float gg = g1[tid], bb = be1[tid];
    __half* yb = h_xln + ((size_t)b * kN + n0) * kC;
    #pragma unroll
    for (int it = 0; it < 32; ++it)
        yb[(size_t)it * kC + tid] = __float2half((s[it][tid] - smu[it]) * srs[it] * gg + bb);
}

// ---------------- fp16 tensor GEMM 128x128x64 ----------------
// MODE 0: fp16 + bias.  MODE 1: fp16 + bias + ReLU.
// MODE 2: fp32 out (B,C,N), bias + residual + transpose.
// MODE 3: QKV: q/k -> chunked h_qkT (q scaled 1/8); v -> h_v.
// MODE 4: proj + fused LN2.
template <int MODE>
__global__ __launch_bounds__(256, 2) void gemm_h(const __half* __restrict__ A,
                                                 const __half* __restrict__ W,
                                                 const float* __restrict__ bias,
                                                 void* __restrict__ Yv,
                                                 const float* __restrict__ xres,
                                                 const float* __restrict__ gam,
                                                 const float* __restrict__ bet,
                                                 int K, int O)
{
    extern __shared__ __align__(16) char smem[];
    const uint32_t sbase = smem_u32(smem);
    const int tid = threadIdx.x;
    const int lane = tid & 31;
    const int wid = tid >> 5;
    const int g  = lane >> 2;
    const int t4 = lane & 3;
    const int wm = wid >> 1;
    const int wn = wid & 1;
    const int m0 = blockIdx.y * 128;
    const int NC = K >> 6;

    const int r_ld = tid >> 3;
    const int c_ld = tid & 7;

    const int quad = lane >> 3, lr = lane & 7;
    const uint32_t offA = (uint32_t)(wm * 32 + (quad & 1) * 8 + lr) * ROWB + (quad >> 1) * 16;
    const uint32_t offB = (uint32_t)(wn * 64 + (quad & 1) * 8 + lr) * ROWB + (quad >> 1) * 16;

    float acc[2][8][4];

    const int n_iters = (MODE == 4) ? 2 : 1;
    int n0 = (MODE == 4) ? 0 : blockIdx.x * 128;

    for (int ni = 0; ni < n_iters; ++ni) {
        if (MODE == 4) n0 = ni * 128;

        #pragma unroll
        for (int i = 0; i < 2; ++i)
            #pragma unroll
            for (int j = 0; j < 8; ++j)
                #pragma unroll
                for (int r = 0; r < 4; ++r) acc[i][j][r] = 0.f;

        auto load_stage = [&](int t) {
            const int bstg = t % NSTG;
            const uint32_t sA = sbase + bstg * STAGEB;
            const uint32_t sB = sA + TILEB;
            const int k0 = t * 64;
            const __half* Ag = A + (size_t)(m0 + r_ld) * K + k0 + c_ld * 8;
            const __half* Wg = W + (size_t)(n0 + r_ld) * K + k0 + c_ld * 8;
            #pragma unroll
            for (int p = 0; p < 4; ++p) {
                cp_async16(sA + (p * 32 + r_ld) * ROWB + c_ld * 16, Ag + (size_t)(p * 32) * K);
                cp_async16(sB + (p * 32 + r_ld) * ROWB + c_ld * 16, Wg + (size_t)(p * 32) * K);
            }
        };

        load_stage(0); CP_COMMIT();
        load_stage(1); CP_COMMIT();

        for (int t = 0; t < NC; ++t) {
            CP_WAIT1();
            __syncthreads();
            if (t + 2 < NC) { load_stage(t + 2); }
            CP_COMMIT();

            const uint32_t fAb = sbase + (t % NSTG) * STAGEB;
            const uint32_t fBb = fAb + TILEB;

            #pragma unroll
            for (int ks = 0; ks < 4; ++ks) {
                uint32_t a[2][4], bq[4][4];
                ldsm4(a[0], fAb + offA + ks * 32);
                ldsm4(a[1], fAb + offA + 16 * ROWB + ks * 32);
                #pragma unroll
                for (int p = 0; p < 4; ++p)
                    ldsm4(bq[p], fBb + offB + p * 16 * ROWB + ks * 32);
                #pragma unroll
                for (int mt = 0; mt < 2; ++mt)
                    #pragma unroll
                    for (int p = 0; p < 4; ++p) {
                        mma_f16(acc[mt][2 * p],     a[mt][0], a[mt][1], a[mt][2], a[mt][3],
                                bq[p][0], bq[p][2]);
                        mma_f16(acc[mt][2 * p + 1], a[mt][0], a[mt][1], a[mt][2], a[mt][3],
                                bq[p][1], bq[p][3]);
                    }
            }
        }
        CP_WAIT0();
        __syncthreads();

        if (MODE == 4 && ni == 0) {
            const uint32_t stg_b = sbase;
            float2 bv[8];
            #pragma unroll
            for (int nt = 0; nt < 8; ++nt)
                bv[nt] = *(const float2*)(bias + n0 + wn * 64 + nt * 8 + t4 * 2);
            const int q2 = lane >> 3, lr2 = lane & 7;
            #pragma unroll
            for (int mt = 0; mt < 2; ++mt) {
                #pragma unroll
                for (int np = 0; np < 4; ++np) {
                    const int e0 = 2 * np, e1 = 2 * np + 1;
                    uint32_t r[4] = {
                        pack_h2(acc[mt][e0][0] + bv[e0].x, acc[mt][e0][1] + bv[e0].y),
                        pack_h2(acc[mt][e0][2] + bv[e0].x, acc[mt][e0][3] + bv[e0].y),
                        pack_h2(acc[mt][e1][0] + bv[e1].x, acc[mt][e1][1] + bv[e1].y),
                        pack_h2(acc[mt][e1][2] + bv[e1].x, acc[mt][e1][3] + bv[e1].y) };
                    const uint32_t ad = stg_b
                        + (uint32_t)(wm * 32 + mt * 16 + (q2 & 1) * 8 + lr2) * 272
                        + (uint32_t)(wn * 64 + np * 16 + (q2 >> 1) * 8) * 2;
                    stsm4(ad, r);
                }
            }
            __syncthreads();
            const __half* S = (const __half*)smem;
            #pragma unroll
            for (int it = 0; it < 8; ++it) {
                const int id = tid + it * 256;
                const int row = id >> 4, seg = id & 15;
                *(uint4*)(h_proj + (size_t)(m0 + row) * 256 + seg * 8) =
                    *(const uint4*)(S + row * 136 + seg * 8);
            }
            __syncthreads();
        }
    }

    if (MODE == 0 || MODE == 1) {
        const uint32_t stg_b = sbase;
        float2 bv[8];
        #pragma unroll
        for (int nt = 0; nt < 8; ++nt)
            bv[nt] = *(const float2*)(bias + n0 + wn * 64 + nt * 8 + t4 * 2);
        const int q2 = lane >> 3, lr2 = lane & 7;
        #pragma unroll
        for (int mt = 0; mt < 2; ++mt) {
            #pragma unroll
            for (int np = 0; np < 4; ++np) {
                const int e0 = 2 * np, e1 = 2 * np + 1;
                float v0 = acc[mt][e0][0] + bv[e0].x, v1 = acc[mt][e0][1] + bv[e0].y;
                float v2 = acc[mt][e0][2] + bv[e0].x, v3 = acc[mt][e0][3] + bv[e0].y;
                float w0 = acc[mt][e1][0] + bv[e1].x, w1 = acc[mt][e1][1] + bv[e1].y;
                float w2 = acc[mt][e1][2] + bv[e1].x, w3 = acc[mt][e1][3] + bv[e1].y;
                if (MODE == 1) {
                    v0 = fmaxf(v0, 0.f); v1 = fmaxf(v1, 0.f);
                    v2 = fmaxf(v2, 0.f); v3 = fmaxf(v3, 0.f);
                    w0 = fmaxf(w0, 0.f); w1 = fmaxf(w1, 0.f);
                    w2 = fmaxf(w2, 0.f); w3 = fmaxf(w3, 0.f);
                }
                uint32_t r[4] = { pack_h2(v0, v1), pack_h2(v2, v3),
                                  pack_h2(w0, w1), pack_h2(w2, w3) };
                const uint32_t ad = stg_b
                    + (uint32_t)(wm * 32 + mt * 16 + (q2 & 1) * 8 + lr2) * 272
                    + (uint32_t)(wn * 64 + np * 16 + (q2 >> 1) * 8) * 2;
                stsm4(ad, r);
            }
        }
        __syncthreads();
        const __half* S = (const __half*)smem;
        __half* Y = (__half*)Yv;
        #pragma unroll
        for (int it = 0; it < 8; ++it) {
            const int id = tid + it * 256;
            const int row = id >> 4, seg = id & 15;
            *(uint4*)(Y + (size_t)(m0 + row) * O + n0 + seg * 8) =
                *(const uint4*)(S + row * 136 + seg * 8);
        }
        return;
    }

    if (MODE == 4) {
        const uint32_t stg_b = sbase;
        float2 bv[8];
        #pragma unroll
        for (int nt = 0; nt < 8; ++nt)
            bv[nt] = *(const float2*)(bias + 128 + wn * 64 + nt * 8 + t4 * 2);
        const int q2 = lane >> 3, lr2 = lane & 7;
        #pragma unroll
        for (int mt = 0; mt < 2; ++mt) {
            #pragma unroll
            for (int np = 0; np < 4; ++np) {
                const int e0 = 2 * np, e1 = 2 * np + 1;
                uint32_t r[4] = {
                    pack_h2(acc[mt][e0][0] + bv[e0].x, acc[mt][e0][1] + bv[e0].y),
                    pack_h2(acc[mt][e0][2] + bv[e0].x, acc[mt][e0][3] + bv[e0].y),
                    pack_h2(acc[mt][e1][0] + bv[e1].x, acc[mt][e1][1] + bv[e1].y),
                    pack_h2(acc[mt][e1][2] + bv[e1].x, acc[mt][e1][3] + bv[e1].y) };
                const uint32_t ad = stg_b
                    + (uint32_t)(wm * 32 + mt * 16 + (q2 & 1) * 8 + lr2) * 272
                    + (uint32_t)(wn * 64 + np * 16 + (q2 >> 1) * 8) * 2;
                stsm4(ad, r);
            }
        }
        float* sgb = (float*)(smem + 36864);
        if (tid < 256) { sgb[tid] = gam[tid]; sgb[256 + tid] = bet[tid]; }
        __syncthreads();

        const int row = tid >> 1, half = tid & 1;
        const uint4* src = half
            ? (const uint4*)((const __half*)smem + row * 136)
            : (const uint4*)(h_proj + (size_t)(m0 + row) * 256);
        float sum = 0.f, sq = 0.f;
        #pragma unroll
        for (int i = 0; i < 16; ++i) {
            uint4 u = src[i];
            const __half2* hh = (const __half2*)&u;
            #pragma unroll
            for (int q = 0; q < 4; ++q) {
                float2 f = __half22float2(hh[q]);
                sum += f.x + f.y;
                sq  += f.x * f.x + f.y * f.y;
            }
        }
        sum += __shfl_xor_sync(0xffffffffu, sum, 1);
        sq  += __shfl_xor_sync(0xffffffffu, sq, 1);
        const float mu = sum * (1.f / 256.f);
        const float rs = rsqrtf(sq * (1.f / 256.f) - mu * mu + 1e-5f);

        __half* Y = (__half*)Yv;
        __half* dst = Y + (size_t)(m0 + row) * 256 + half * 128;
        const float* gp = sgb + half * 128;
        const float* bp = sgb + 256 + half * 128;
        #pragma unroll
        for (int i = 0; i < 16; ++i) {
            uint4 u = src[i];
            const __half2* hh = (const __half2*)&u;
            __half2 o[4];
            #pragma unroll
            for (int q = 0; q < 4; ++q) {
                float2 f = __half22float2(hh[q]);
                const int c = i * 8 + q * 2;
                o[q] = __floats2half2_rn((f.x - mu) * rs * gp[c]     + bp[c],
                                         (f.y - mu) * rs * gp[c + 1] + bp[c + 1]);
            }
            *(uint4*)(dst + i * 8) = *(uint4*)o;
        }
        return;
    }

    float* stg = (float*)smem;
    #pragma unroll
    for (int mt = 0; mt < 2; ++mt) {
        #pragma unroll
        for (int nt = 0; nt < 8; ++nt) {
            const int row = wm * 32 + mt * 16 + g;
            const int col = wn * 64 + nt * 8 + t4 * 2;
            stg[row * 133 + col]           = acc[mt][nt][0];
            stg[row * 133 + col + 1]       = acc[mt][nt][1];
            stg[(row + 8) * 133 + col]     = acc[mt][nt][2];
            stg[(row + 8) * 133 + col + 1] = acc[mt][nt][3];
        }
    }
    __syncthreads();

    if (MODE == 2) {
        float* Y = (float*)Yv;
        const int bidx = m0 >> 12;
        const int npix = m0 & 4095;
        #pragma unroll
        for (int ci = 0; ci < 16; ++ci) {
            const int c = wid * 16 + ci;
            const int cg = n0 + c;
            const float bv = bias[cg];
            const size_t base = (((size_t)(bidx * 256 + cg)) << 12) + npix;
            #pragma unroll
            for (int i = 0; i < 4; ++i) {
                const int m = lane + 32 * i;
                Y[base + m] = stg[m * 133 + c] + bv + xres[base + m];
            }
        }
    } else {  // MODE 3
        if (n0 < 512) {
            const int bidx = m0 >> 12;
            const int npix = m0 & 4095;
            const int ch   = npix >> 9;
            const int nl   = npix & 511;
            #pragma unroll
            for (int ci = 0; ci < 16; ++ci) {
                const int c  = wid * 16 + ci;
                const int cg = n0 + c;
                const int qk = cg >> 8;
                const int hh = (cg >> 6) & 3;
                const int d  = cg & 63;
                const float sc = qk ? 1.f : 0.125f;
                const float bv = bias[cg];
                const int blk = (qk * 8 + bidx) * 4 + hh;
                __half* rp = h_qkT + ((size_t)((blk * 8 + ch) * 64 + d)) * 512
                           + nl + lane * 4;
                float v0 = (stg[(lane * 4 + 0) * 133 + c] + bv) * sc;
                float v1 = (stg[(lane * 4 + 1) * 133 + c] + bv) * sc;
                float v2 = (stg[(lane * 4 + 2) * 133 + c] + bv) * sc;
                float v3 = (stg[(lane * 4 + 3) * 133 + c] + bv) * sc;
                __half2 o[2] = { __floats2half2_rn(v0, v1), __floats2half2_rn(v2, v3) };
                *(uint2*)rp = *(uint2*)o;
            }
        } else {
            const int rr = tid >> 1;
            const int cb = (tid & 1) * 64;
            __half* yp = h_v + (size_t)(m0 + rr) * 256 + (n0 - 512) + cb;
            const float* bp = bias + n0 + cb;
            #pragma unroll
            for (int i = 0; i < 8; ++i) {
                __half2 h[4];
                #pragma unroll
                for (int q = 0; q < 4; ++q) {
                    float v0 = stg[rr * 133 + cb + i * 8 + q * 2]     + bp[i * 8 + q * 2];
                    float v1 = stg[rr * 133 + cb + i * 8 + q * 2 + 1] + bp[i * 8 + q * 2 + 1];
                    h[q] = __floats2half2_rn(v0, v1);
                }
                *(uint4*)(yp + i * 8) = *(uint4*)h;
            }
        }
    }
}

// ---------------- attention S (split-K x16; two CTAs per 512-chunk) ----------------
__global__ __launch_bounds__(128) void attn_s_tc()
{
    const int bh = blockIdx.x, ch = blockIdx.y;    // ch 0..15
    const int chunk = ch >> 1, halfc = ch & 1;     // 512-chunk, 256-col half
    const int b = bh >> 2, h = bh & 3;
    __shared__ __align__(16) char sbuf[2][2 * 64 * 144];
    const int tid = threadIdx.x, lane = tid & 31, w = tid >> 5;
    const uint32_t s0 = smem_u32(sbuf);
    const __half* qg = h_qkT + ((size_t)(((b * 4 + h) * 8 + chunk) * 64)) * 512 + halfc * 256;
    const __half* kg = h_qkT + ((size_t)(((32 + b * 4 + h) * 8 + chunk) * 64)) * 512 + halfc * 256;

    auto load = [&](int c) {
        const uint32_t buf = s0 + (c & 1) * (2 * 64 * 144);
        const int kk = c * 64;
        #pragma unroll
        for (int j = 0; j < 4; ++j) {
            int idx = j * 128 + tid;
            int row = idx >> 3, c8 = idx & 7;
            cp_async16(buf + row * 144 + c8 * 16,
                       qg + (size_t)row * 512 + kk + c8 * 8);
            cp_async16(buf + 64 * 144 + row * 144 + c8 * 16,
                       kg + (size_t)row * 512 + kk + c8 * 8);
        }
    };

    float acc[8][4];
    #pragma unroll
    for (int j = 0; j < 8; ++j)
        #pragma unroll
        for (int r = 0; r < 4; ++r) acc[j][r] = 0.f;

    const int quad = lane >> 3, lr = lane & 7;
    const uint32_t offA = (uint32_t)(w * 16 + (quad & 1) * 8 + lr) * 144 + (quad >> 1) * 16;
    const uint32_t offB = (uint32_t)((quad & 1) * 8 + lr) * 144 + (quad >> 1) * 16;

    load(0); CP_COMMIT();
    for (int c = 0; c < 4; ++c) {
        CP_WAIT0();
        __syncthreads();
        if (c < 3) { load(c + 1); CP_COMMIT(); }
        const uint32_t qs  = s0 + (c & 1) * (2 * 64 * 144);
        const uint32_t ks_ = qs + 64 * 144;
        #pragma unroll
        for (int kh = 0; kh < 4; ++kh) {
            uint32_t a[4], bq[4][4];
            ldsm4(a, qs + offA + kh * 32);
            #pragma unroll
            for (int p = 0; p < 4; ++p)
                ldsm4(bq[p], ks_ + offB + p * 16 * 144 + kh * 32);
            #pragma unroll
            for (int p = 0; p < 4; ++p) {
                mma_f16(acc[2 * p],     a[0], a[1], a[2], a[3], bq[p][0], bq[p][2]);
                mma_f16(acc[2 * p + 1], a[0], a[1], a[2], a[3], bq[p][1], bq[p][3]);
            }
        }
    }

    const int g = lane >> 2, t4 = lane & 3;
    float* sp = g_spart + (size_t)(bh * kNCH + ch) * 64 * 64;
    #pragma unroll
    for (int nt = 0; nt < 8; ++nt) {
        const int row = w * 16 + g, col = nt * 8 + t4 * 2;
        sp[row * 64 + col]           = acc[nt][0];
        sp[row * 64 + col + 1]       = acc[nt][1];
        sp[(row + 8) * 64 + col]     = acc[nt][2];
        sp[(row + 8) * 64 + col + 1] = acc[nt][3];
    }
}

// ---------------- softmax ----------------
__global__ __launch_bounds__(256) void softmax_kernel()
{
    int bh = blockIdx.x;
    int dd = blockIdx.y * 8 + (threadIdx.x >> 5);
    int lane = threadIdx.x & 31;
    const float* spb = g_spart + (size_t)bh * kNCH * 64 * 64 + dd * 64;
    float v0 = 0.f, v1 = 0.f;
    #pragma unroll
    for (int p = 0; p < kNCH; ++p) {
        v0 += spb[(size_t)p * 64 * 64 + lane];
        v1 += spb[(size_t)p * 64 * 64 + 32 + lane];
    }
    float m = fmaxf(v0, v1);
    #pragma unroll
    for (int off = 16; off; off >>= 1) m = fmaxf(m, __shfl_xor_sync(0xffffffffu, m, off));
    v0 = expf(v0 - m); v1 = expf(v1 - m);
    float s = v0 + v1;
    #pragma unroll
    for (int off = 16; off; off >>= 1) s += __shfl_xor_sync(0xffffffffu, s, off);
    float inv = 1.f / s;
    __half* at = h_attnw + (size_t)bh * 64 * 64 + dd * 64;
    at[lane]      = __float2half(v0 * inv);
    at[32 + lane] = __float2half(v1 * inv);
}

// ---------------- AV ----------------
__global__ __launch_bounds__(128) void attn_av_tc()
{
    const int bh = blockIdx.y, b = bh >> 2, h = bh & 3;
    const int n0 = blockIdx.x * 128;
    __shared__ __align__(16) __half sV[128 * 72];
    __shared__ __align__(16) __half sA[64 * 72];
    const int tid = threadIdx.x, lane = tid & 31, w = tid >> 5;
    const uint32_t vb = smem_u32(sV), ab = smem_u32(sA);

    #pragma unroll
    for (int j = 0; j < 8; ++j) {
        int idx = tid + j * 128;
        int row = idx >> 3, c8 = idx & 7;
        cp_async16(vb + row * 144 + c8 * 16,
                   h_v + ((size_t)(b * 4096 + n0 + row)) * 256 + h * 64 + c8 * 8);
    }
    #pragma unroll
    for (int j = 0; j < 4; ++j) {
        int idx = tid + j * 128;
        int row = idx >> 3, c8 = idx & 7;
        cp_async16(ab + row * 144 + c8 * 16,
                   h_attnw + (size_t)bh * 4096 + row * 64 + c8 * 8);
    }
    CP_COMMIT();
    CP_WAIT0();
    __syncthreads();

    const int quad = lane >> 3, lr = lane & 7;
    const uint32_t offA = (uint32_t)(w * 32 + (quad & 1) * 8 + lr) * 144 + (quad >> 1) * 16;
    const uint32_t offB = (uint32_t)((quad & 1) * 8 + lr) * 144 + (quad >> 1) * 16;

    float acc[2][8][4];
    #pragma unroll
    for (int i = 0; i < 2; ++i)
        #pragma unroll
        for (int j = 0; j < 8; ++j)
            #pragma unroll
            for (int r = 0; r < 4; ++r) acc[i][j][r] = 0.f;

    #pragma unroll
    for (int ks = 0; ks < 4; ++ks) {
        uint32_t a[2][4], bq[4][4];
        ldsm4(a[0], vb + offA + ks * 32);
        ldsm4(a[1], vb + offA + 16 * 144 + ks * 32);
        #pragma unroll
        for (int p = 0; p < 4; ++p)
            ldsm4(bq[p], ab + offB + p * 16 * 144 + ks * 32);
        #pragma unroll
        for (int mt = 0; mt < 2; ++mt)
            #pragma unroll
            for (int p = 0; p < 4; ++p) {
                mma_f16(acc[mt][2 * p],     a[mt][0], a[mt][1], a[mt][2], a[mt][3],
                        bq[p][0], bq[p][2]);
                mma_f16(acc[mt][2 * p + 1], a[mt][0], a[mt][1], a[mt][2], a[mt][3],
                        bq[p][1], bq[p][3]);
            }
    }

    const int g = lane >> 2, t4 = lane & 3;
    #pragma unroll
    for (int mt = 0; mt < 2; ++mt) {
        #pragma unroll
        for (int nt = 0; nt < 8; ++nt) {
            const int n1 = n0 + w * 32 + mt * 16 + g;
            const int d  = nt * 8 + t4 * 2;
            __half* yp = h_attnout + ((size_t)(b * 4096 + n1)) * 256 + h * 64 + d;
            *(__half2*)yp = __floats2half2_rn(acc[mt][nt][0], acc[mt][nt][1]);
            *(__half2*)(yp + 8 * 256) = __floats2half2_rn(acc[mt][nt][2], acc[mt][nt][3]);
        }
    }
}

// ---------------- launch ----------------
extern "C" void kernel_launch(void* const* d_in, const int* in_sizes, int n_in,
                              void* d_out, int out_size)
{
    const float* x      = (const float*)d_in[0];
    const float* w_qkv  = (const float*)d_in[1];
    const float* b_qkv  = (const float*)d_in[2];
    const float* w_proj = (const float*)d_in[3];
    const float* b_proj = (const float*)d_in[4];
    const float* w_ffn1 = (const float*)d_in[5];
    const float* b_ffn1 = (const float*)d_in[6];
    const float* w_ffn2 = (const float*)d_in[7];
    const float* b_ffn2 = (const float*)d_in[8];
    const float* g1     = (const float*)d_in[9];
    const float* be1    = (const float*)d_in[10];
    const float* g2     = (const float*)d_in[11];
    const float* be2    = (const float*)d_in[12];
    float* out = (float*)d_out;

    void *p_xln, *p_attnout, *p_ln2, *p_ffh, *p_w;
    cudaGetSymbolAddress(&p_xln, h_xln);
    cudaGetSymbolAddress(&p_attnout, h_attnout);
    cudaGetSymbolAddress(&p_ln2, h_ln2);
    cudaGetSymbolAddress(&p_ffh, h_ffh);
    cudaGetSymbolAddress(&p_w, h_w);
    const __half* hw = (const __half*)p_w;

    cudaFuncSetAttribute(gemm_h<1>, cudaFuncAttributeMaxDynamicSharedMemorySize, SMEM_DYN);
    cudaFuncSetAttribute(gemm_h<2>, cudaFuncAttributeMaxDynamicSharedMemorySize, SMEM_DYN);
    cudaFuncSetAttribute(gemm_h<3>, cudaFuncAttributeMaxDynamicSharedMemorySize, SMEM_DYN);
    cudaFuncSetAttribute(gemm_h<4>, cudaFuncAttributeMaxDynamicSharedMemorySize, SMEM_DYN);

    const int M = kB * kN;  // 32768

    convw_kernel<<<(OW_TOT + 255) / 256, 256>>>(w_qkv, w_proj, w_ffn1, w_ffn2);

    ln1_kernel<<<dim3(kN / 32, kB), 256>>>(x, g1, be1);

    gemm_h<3><<<dim3(kC3 / 128, M / 128), 256, SMEM_DYN>>>(
        (const __half*)p_xln, hw + OW_QKV, b_qkv, nullptr, nullptr, nullptr, nullptr, kC, kC3);

    attn_s_tc<<<dim3(kBH, kNCH), 128>>>();
    softmax_kernel<<<dim3(kBH, 8), 256>>>();
    attn_av_tc<<<dim3(kN / 128, kBH), 128>>>();

    // proj + fused LN2 -> h_ln2
    gemm_h<4><<<dim3(1, M / 128), 256, SMEM_DYN>>>(
        (const __half*)p_attnout, hw + OW_PROJ, b_proj, p_ln2, nullptr, g2, be2, kC, kC);

    gemm_h<1><<<dim3(kFFN / 128, M / 128), 256, SMEM_DYN>>>(
        (const __half*)p_ln2, hw + OW_FFN1, b_ffn1, p_ffh, nullptr, nullptr, nullptr, kC, kFFN);

    gemm_h<2><<<dim3(kC / 128, M / 128), 256, SMEM_DYN>>>(
        (const __half*)p_ffh, hw + OW_FFN2, b_ffn2, out, x, nullptr, nullptr, kFFN, kC);
}

// round 13
// speedup vs baseline: 1.0205x; 1.0205x over previous
#include <cuda_runtime.h>
#include <cuda_fp16.h>
#include <cstdint>

// ---------------- problem constants ----------------
namespace {
constexpr int kB   = 8;
constexpr int kC   = 256;
constexpr int kN   = 4096;
constexpr int kC3  = 768;
constexpr int kFFN = 2048;
constexpr int kBH  = 32;
constexpr int kNCH = 16;     // 16 split-K CTAs per bh; pairs share one 512-n chunk

constexpr int ROWB   = 144;
constexpr int TILEB  = 128 * ROWB;
constexpr int STAGEB = 2 * TILEB;
constexpr int NSTG   = 3;
constexpr uint32_t SMEM_DYN = STAGEB * NSTG; // 110592 (2 CTAs/SM)

constexpr int OW_QKV  = 0;
constexpr int OW_PROJ = OW_QKV + kC3 * kC;
constexpr int OW_FFN1 = OW_PROJ + kC * kC;
constexpr int OW_FFN2 = OW_FFN1 + kFFN * kC;
constexpr int OW_TOT  = OW_FFN2 + kC * kFFN;
}

// ---------------- scratch ----------------
__device__ __half h_xln[kB * kN * kC];
// chunked q/k layout: [blk(64)][ch(8)][d(64)][nl(512)], blk=(qk*8+b)*4+h
__device__ __half h_qkT[4096 * 4096];
__device__ __half h_v[kB * kN * kC];
__device__ float  g_spart[kBH * kNCH * 64 * 64];
__device__ __half h_attnw[kBH * 64 * 64];
__device__ __half h_attnout[kB * kN * kC];
__device__ __half h_proj[kB * kN * kC];
__device__ __half h_ln2[kB * kN * kC];
__device__ __half h_ffh[kB * kN * kFFN];
__device__ __half h_w[OW_TOT];

// ---------------- helpers ----------------
__device__ __forceinline__ uint32_t smem_u32(const void* p) {
    uint32_t a;
    asm("{ .reg .u64 t; cvta.to.shared.u64 t, %1; cvt.u32.u64 %0, t; }" : "=r"(a) : "l"(p));
    return a;
}
__device__ __forceinline__ void cp_async16(uint32_t s, const void* g) {
    asm volatile("cp.async.cg.shared.global [%0], [%1], 16;" :: "r"(s), "l"(g));
}
#define CP_COMMIT() asm volatile("cp.async.commit_group;" ::: "memory")
#define CP_WAIT1()  asm volatile("cp.async.wait_group 1;" ::: "memory")
#define CP_WAIT0()  asm volatile("cp.async.wait_group 0;" ::: "memory")

__device__ __forceinline__ void ldsm4(uint32_t* r, uint32_t a) {
    asm volatile("ldmatrix.sync.aligned.m8n8.x4.shared.b16 {%0,%1,%2,%3}, [%4];"
                 : "=r"(r[0]), "=r"(r[1]), "=r"(r[2]), "=r"(r[3]) : "r"(a));
}
__device__ __forceinline__ void stsm4(uint32_t a, const uint32_t* r) {
    asm volatile("stmatrix.sync.aligned.m8n8.x4.shared.b16 [%0], {%1,%2,%3,%4};"
                 :: "r"(a), "r"(r[0]), "r"(r[1]), "r"(r[2]), "r"(r[3]) : "memory");
}
__device__ __forceinline__ void mma_f16(float* c,
                                        uint32_t a0, uint32_t a1, uint32_t a2, uint32_t a3,
                                        uint32_t b0, uint32_t b1) {
    asm volatile(
        "mma.sync.aligned.m16n8k16.row.col.f32.f16.f16.f32 "
        "{%0,%1,%2,%3}, {%4,%5,%6,%7}, {%8,%9}, {%0,%1,%2,%3};"
        : "+f"(c[0]), "+f"(c[1]), "+f"(c[2]), "+f"(c[3])
        : "r"(a0), "r"(a1), "r"(a2), "r"(a3), "r"(b0), "r"(b1));
}
__device__ __forceinline__ uint32_t pack_h2(float x, float y) {
    __half2 h = __floats2half2_rn(x, y);
    return *(uint32_t*)&h;
}

// ---------------- weight conversion ----------------
__global__ __launch_bounds__(256) void convw_kernel(const float* __restrict__ wqkv,
                                                    const float* __restrict__ wproj,
                                                    const float* __restrict__ wffn1,
                                                    const float* __restrict__ wffn2)
{
    int i = blockIdx.x * 256 + threadIdx.x;
    if (i >= OW_TOT) return;
    float v;
    if (i < OW_PROJ)       v = wqkv[i - OW_QKV];
    else if (i < OW_FFN1)  v = wproj[i - OW_PROJ];
    else if (i < OW_FFN2)  v = wffn1[i - OW_FFN1];
    else                   v = wffn2[i - OW_FFN2];
    h_w[i] = __float2half(v);
}

// ---------------- LN1 ----------------
__global__ __launch_bounds__(256) void ln1_kernel(const float* __restrict__ x,
                                                  const float* __restrict__ g1,
                                                  const float* __restrict__ be1)
{
    __shared__ float s[32][257];
    __shared__ float smu[32], srs[32];
    int b  = blockIdx.y;
    int n0 = blockIdx.x * 32;
    int tid = threadIdx.x;
    const float* xb = x + (size_t)b * kC * kN;
    #pragma unroll
    for (int it = 0; it < 32; ++it) {
        int idx = it * 256 + tid;
        int c = idx >> 5, nn = idx & 31;
        s[nn][c] = xb[(size_t)c * kN + n0 + nn];
    }
    __syncthreads();
    int nn = tid >> 3, g = tid & 7;
    float sum = 0.f, sq = 0.f;
    #pragma unroll
    for (int j = 0; j < 32; ++j) { float v = s[nn][g + j * 8]; sum += v; sq += v * v; }
    sum += __shfl_xor_sync(0xffffffffu, sum, 1, 8);
    sum += __shfl_xor_sync(0xffffffffu, sum, 2, 8);
    sum += __shfl_xor_sync(0xffffffffu, sum, 4, 8);
    sq  += __shfl_xor_sync(0xffffffffu, sq, 1, 8);
    sq  += __shfl_xor_sync(0xffffffffu, sq, 2, 8);
    sq  += __shfl_xor_sync(0xffffffffu, sq, 4, 8);
    if (g == 0) {
        float mu = sum * (1.f / 256.f);
        smu[nn] = mu;
        srs[nn] = rsqrtf(sq * (1.f / 256.f) - mu * mu + 1e-5f);
    }
    __syncthreads();
    float gg = g1[tid], bb = be1[tid];
    __half* yb = h_xln + ((size_t)b * kN + n0) * kC;
    #pragma unroll
    for (int it = 0; it < 32; ++it)
        yb[(size_t)it * kC + tid] = __float2half((s[it][tid] - smu[it]) * srs[it] * gg + bb);
}

// ---------------- fp16 tensor GEMM 128x128x64 ----------------
// MODE 0: fp16 + bias.  MODE 1: fp16 + bias + ReLU.
// MODE 2: fp32 out (B,C,N), bias + residual + transpose.
// MODE 3: QKV q/k -> chunked h_qkT (q scaled 1/8).
// MODE 4: proj + fused LN2.
template <int MODE>
__global__ __launch_bounds__(256, 2) void gemm_h(const __half* __restrict__ A,
                                                 const __half* __restrict__ W,
                                                 const float* __restrict__ bias,
                                                 void* __restrict__ Yv,
                                                 const float* __restrict__ xres,
                                                 const float* __restrict__ gam,
                                                 const float* __restrict__ bet,
                                                 int K, int O)
{
    extern __shared__ __align__(16) char smem[];
    const uint32_t sbase = smem_u32(smem);
    const int tid = threadIdx.x;
    const int lane = tid & 31;
    const int wid = tid >> 5;
    const int g  = lane >> 2;
    const int t4 = lane & 3;
    const int wm = wid >> 1;
    const int wn = wid & 1;
    const int m0 = blockIdx.y * 128;
    const int NC = K >> 6;

    const int r_ld = tid >> 3;
    const int c_ld = tid & 7;

    const int quad = lane >> 3, lr = lane & 7;
    const uint32_t offA = (uint32_t)(wm * 32 + (quad & 1) * 8 + lr) * ROWB + (quad >> 1) * 16;
    const uint32_t offB = (uint32_t)(wn * 64 + (quad & 1) * 8 + lr) * ROWB + (quad >> 1) * 16;

    float acc[2][8][4];

    const int n_iters = (MODE == 4) ? 2 : 1;
    int n0 = (MODE == 4) ? 0 : blockIdx.x * 128;

    for (int ni = 0; ni < n_iters; ++ni) {
        if (MODE == 4) n0 = ni * 128;

        #pragma unroll
        for (int i = 0; i < 2; ++i)
            #pragma unroll
            for (int j = 0; j < 8; ++j)
                #pragma unroll
                for (int r = 0; r < 4; ++r) acc[i][j][r] = 0.f;

        auto load_stage = [&](int t) {
            const int bstg = t % NSTG;
            const uint32_t sA = sbase + bstg * STAGEB;
            const uint32_t sB = sA + TILEB;
            const int k0 = t * 64;
            const __half* Ag = A + (size_t)(m0 + r_ld) * K + k0 + c_ld * 8;
            const __half* Wg = W + (size_t)(n0 + r_ld) * K + k0 + c_ld * 8;
            #pragma unroll
            for (int p = 0; p < 4; ++p) {
                cp_async16(sA + (p * 32 + r_ld) * ROWB + c_ld * 16, Ag + (size_t)(p * 32) * K);
                cp_async16(sB + (p * 32 + r_ld) * ROWB + c_ld * 16, Wg + (size_t)(p * 32) * K);
            }
        };

        load_stage(0); CP_COMMIT();
        load_stage(1); CP_COMMIT();

        for (int t = 0; t < NC; ++t) {
            CP_WAIT1();
            __syncthreads();
            if (t + 2 < NC) { load_stage(t + 2); }
            CP_COMMIT();

            const uint32_t fAb = sbase + (t % NSTG) * STAGEB;
            const uint32_t fBb = fAb + TILEB;

            #pragma unroll
            for (int ks = 0; ks < 4; ++ks) {
                uint32_t a[2][4], bq[4][4];
                ldsm4(a[0], fAb + offA + ks * 32);
                ldsm4(a[1], fAb + offA + 16 * ROWB + ks * 32);
                #pragma unroll
                for (int p = 0; p < 4; ++p)
                    ldsm4(bq[p], fBb + offB + p * 16 * ROWB + ks * 32);
                #pragma unroll
                for (int mt = 0; mt < 2; ++mt)
                    #pragma unroll
                    for (int p = 0; p < 4; ++p) {
                        mma_f16(acc[mt][2 * p],     a[mt][0], a[mt][1], a[mt][2], a[mt][3],
                                bq[p][0], bq[p][2]);
                        mma_f16(acc[mt][2 * p + 1], a[mt][0], a[mt][1], a[mt][2], a[mt][3],
                                bq[p][1], bq[p][3]);
                    }
            }
        }
        CP_WAIT0();
        __syncthreads();

        if (MODE == 4 && ni == 0) {
            const uint32_t stg_b = sbase;
            float2 bv[8];
            #pragma unroll
            for (int nt = 0; nt < 8; ++nt)
                bv[nt] = *(const float2*)(bias + n0 + wn * 64 + nt * 8 + t4 * 2);
            const int q2 = lane >> 3, lr2 = lane & 7;
            #pragma unroll
            for (int mt = 0; mt < 2; ++mt) {
                #pragma unroll
                for (int np = 0; np < 4; ++np) {
                    const int e0 = 2 * np, e1 = 2 * np + 1;
                    uint32_t r[4] = {
                        pack_h2(acc[mt][e0][0] + bv[e0].x, acc[mt][e0][1] + bv[e0].y),
                        pack_h2(acc[mt][e0][2] + bv[e0].x, acc[mt][e0][3] + bv[e0].y),
                        pack_h2(acc[mt][e1][0] + bv[e1].x, acc[mt][e1][1] + bv[e1].y),
                        pack_h2(acc[mt][e1][2] + bv[e1].x, acc[mt][e1][3] + bv[e1].y) };
                    const uint32_t ad = stg_b
                        + (uint32_t)(wm * 32 + mt * 16 + (q2 & 1) * 8 + lr2) * 272
                        + (uint32_t)(wn * 64 + np * 16 + (q2 >> 1) * 8) * 2;
                    stsm4(ad, r);
                }
            }
            __syncthreads();
            const __half* S = (const __half*)smem;
            #pragma unroll
            for (int it = 0; it < 8; ++it) {
                const int id = tid + it * 256;
                const int row = id >> 4, seg = id & 15;
                *(uint4*)(h_proj + (size_t)(m0 + row) * 256 + seg * 8) =
                    *(const uint4*)(S + row * 136 + seg * 8);
            }
            __syncthreads();
        }
    }

    if (MODE == 0 || MODE == 1) {
        const uint32_t stg_b = sbase;
        float2 bv[8];
        #pragma unroll
        for (int nt = 0; nt < 8; ++nt)
            bv[nt] = *(const float2*)(bias + n0 + wn * 64 + nt * 8 + t4 * 2);
        const int q2 = lane >> 3, lr2 = lane & 7;
        #pragma unroll
        for (int mt = 0; mt < 2; ++mt) {
            #pragma unroll
            for (int np = 0; np < 4; ++np) {
                const int e0 = 2 * np, e1 = 2 * np + 1;
                float v0 = acc[mt][e0][0] + bv[e0].x, v1 = acc[mt][e0][1] + bv[e0].y;
                float v2 = acc[mt][e0][2] + bv[e0].x, v3 = acc[mt][e0][3] + bv[e0].y;
                float w0 = acc[mt][e1][0] + bv[e1].x, w1 = acc[mt][e1][1] + bv[e1].y;
                float w2 = acc[mt][e1][2] + bv[e1].x, w3 = acc[mt][e1][3] + bv[e1].y;
                if (MODE == 1) {
                    v0 = fmaxf(v0, 0.f); v1 = fmaxf(v1, 0.f);
                    v2 = fmaxf(v2, 0.f); v3 = fmaxf(v3, 0.f);
                    w0 = fmaxf(w0, 0.f); w1 = fmaxf(w1, 0.f);
                    w2 = fmaxf(w2, 0.f); w3 = fmaxf(w3, 0.f);
                }
                uint32_t r[4] = { pack_h2(v0, v1), pack_h2(v2, v3),
                                  pack_h2(w0, w1), pack_h2(w2, w3) };
                const uint32_t ad = stg_b
                    + (uint32_t)(wm * 32 + mt * 16 + (q2 & 1) * 8 + lr2) * 272
                    + (uint32_t)(wn * 64 + np * 16 + (q2 >> 1) * 8) * 2;
                stsm4(ad, r);
            }
        }
        __syncthreads();
        const __half* S = (const __half*)smem;
        __half* Y = (__half*)Yv;
        #pragma unroll
        for (int it = 0; it < 8; ++it) {
            const int id = tid + it * 256;
            const int row = id >> 4, seg = id & 15;
            *(uint4*)(Y + (size_t)(m0 + row) * O + n0 + seg * 8) =
                *(const uint4*)(S + row * 136 + seg * 8);
        }
        return;
    }

    if (MODE == 4) {
        const uint32_t stg_b = sbase;
        float2 bv[8];
        #pragma unroll
        for (int nt = 0; nt < 8; ++nt)
            bv[nt] = *(const float2*)(bias + 128 + wn * 64 + nt * 8 + t4 * 2);
        const int q2 = lane >> 3, lr2 = lane & 7;
        #pragma unroll
        for (int mt = 0; mt < 2; ++mt) {
            #pragma unroll
            for (int np = 0; np < 4; ++np) {
                const int e0 = 2 * np, e1 = 2 * np + 1;
                uint32_t r[4] = {
                    pack_h2(acc[mt][e0][0] + bv[e0].x, acc[mt][e0][1] + bv[e0].y),
                    pack_h2(acc[mt][e0][2] + bv[e0].x, acc[mt][e0][3] + bv[e0].y),
                    pack_h2(acc[mt][e1][0] + bv[e1].x, acc[mt][e1][1] + bv[e1].y),
                    pack_h2(acc[mt][e1][2] + bv[e1].x, acc[mt][e1][3] + bv[e1].y) };
                const uint32_t ad = stg_b
                    + (uint32_t)(wm * 32 + mt * 16 + (q2 & 1) * 8 + lr2) * 272
                    + (uint32_t)(wn * 64 + np * 16 + (q2 >> 1) * 8) * 2;
                stsm4(ad, r);
            }
        }
        float* sgb = (float*)(smem + 36864);
        if (tid < 256) { sgb[tid] = gam[tid]; sgb[256 + tid] = bet[tid]; }
        __syncthreads();

        const int row = tid >> 1, half = tid & 1;
        const uint4* src = half
            ? (const uint4*)((const __half*)smem + row * 136)
            : (const uint4*)(h_proj + (size_t)(m0 + row) * 256);
        float sum = 0.f, sq = 0.f;
        #pragma unroll
        for (int i = 0; i < 16; ++i) {
            uint4 u = src[i];
            const __half2* hh = (const __half2*)&u;
            #pragma unroll
            for (int q = 0; q < 4; ++q) {
                float2 f = __half22float2(hh[q]);
                sum += f.x + f.y;
                sq  += f.x * f.x + f.y * f.y;
            }
        }
        sum += __shfl_xor_sync(0xffffffffu, sum, 1);
        sq  += __shfl_xor_sync(0xffffffffu, sq, 1);
        const float mu = sum * (1.f / 256.f);
        const float rs = rsqrtf(sq * (1.f / 256.f) - mu * mu + 1e-5f);

        __half* Y = (__half*)Yv;
        __half* dst = Y + (size_t)(m0 + row) * 256 + half * 128;
        const float* gp = sgb + half * 128;
        const float* bp = sgb + 256 + half * 128;
        #pragma unroll
        for (int i = 0; i < 16; ++i) {
            uint4 u = src[i];
            const __half2* hh = (const __half2*)&u;
            __half2 o[4];
            #pragma unroll
            for (int q = 0; q < 4; ++q) {
                float2 f = __half22float2(hh[q]);
                const int c = i * 8 + q * 2;
                o[q] = __floats2half2_rn((f.x - mu) * rs * gp[c]     + bp[c],
                                         (f.y - mu) * rs * gp[c + 1] + bp[c + 1]);
            }
            *(uint4*)(dst + i * 8) = *(uint4*)o;
        }
        return;
    }

    float* stg = (float*)smem;
    #pragma unroll
    for (int mt = 0; mt < 2; ++mt) {
        #pragma unroll
        for (int nt = 0; nt < 8; ++nt) {
            const int row = wm * 32 + mt * 16 + g;
            const int col = wn * 64 + nt * 8 + t4 * 2;
            stg[row * 133 + col]           = acc[mt][nt][0];
            stg[row * 133 + col + 1]       = acc[mt][nt][1];
            stg[(row + 8) * 133 + col]     = acc[mt][nt][2];
            stg[(row + 8) * 133 + col + 1] = acc[mt][nt][3];
        }
    }
    __syncthreads();

    if (MODE == 2) {
        float* Y = (float*)Yv;
        const int bidx = m0 >> 12;
        const int npix = m0 & 4095;
        #pragma unroll
        for (int ci = 0; ci < 16; ++ci) {
            const int c = wid * 16 + ci;
            const int cg = n0 + c;
            const float bv = bias[cg];
            const size_t base = (((size_t)(bidx * 256 + cg)) << 12) + npix;
            #pragma unroll
            for (int i = 0; i < 4; ++i) {
                const int m = lane + 32 * i;
                Y[base + m] = stg[m * 133 + c] + bv + xres[base + m];
            }
        }
    } else {  // MODE 3 (q/k only; n0 < 512 by grid construction)
        const int bidx = m0 >> 12;
        const int npix = m0 & 4095;
        const int ch   = npix >> 9;
        const int nl   = npix & 511;
        #pragma unroll
        for (int ci = 0; ci < 16; ++ci) {
            const int c  = wid * 16 + ci;
            const int cg = n0 + c;
            const int qk = cg >> 8;
            const int hh = (cg >> 6) & 3;
            const int d  = cg & 63;
            const float sc = qk ? 1.f : 0.125f;
            const float bv = bias[cg];
            const int blk = (qk * 8 + bidx) * 4 + hh;
            __half* rp = h_qkT + ((size_t)((blk * 8 + ch) * 64 + d)) * 512
                       + nl + lane * 4;
            float v0 = (stg[(lane * 4 + 0) * 133 + c] + bv) * sc;
            float v1 = (stg[(lane * 4 + 1) * 133 + c] + bv) * sc;
            float v2 = (stg[(lane * 4 + 2) * 133 + c] + bv) * sc;
            float v3 = (stg[(lane * 4 + 3) * 133 + c] + bv) * sc;
            __half2 o[2] = { __floats2half2_rn(v0, v1), __floats2half2_rn(v2, v3) };
            *(uint2*)rp = *(uint2*)o;
        }
    }
}

// ---------------- attention S (split-K x16; two CTAs per 512-chunk) ----------------
__global__ __launch_bounds__(128) void attn_s_tc()
{
    const int bh = blockIdx.x, ch = blockIdx.y;    // ch 0..15
    const int chunk = ch >> 1, halfc = ch & 1;     // 512-chunk, 256-col half
    const int b = bh >> 2, h = bh & 3;
    __shared__ __align__(16) char sbuf[2][2 * 64 * 144];
    const int tid = threadIdx.x, lane = tid & 31, w = tid >> 5;
    const uint32_t s0 = smem_u32(sbuf);
    const __half* qg = h_qkT + ((size_t)(((b * 4 + h) * 8 + chunk) * 64)) * 512 + halfc * 256;
    const __half* kg = h_qkT + ((size_t)(((32 + b * 4 + h) * 8 + chunk) * 64)) * 512 + halfc * 256;

    auto load = [&](int c) {
        const uint32_t buf = s0 + (c & 1) * (2 * 64 * 144);
        const int kk = c * 64;
        #pragma unroll
        for (int j = 0; j < 4; ++j) {
            int idx = j * 128 + tid;
            int row = idx >> 3, c8 = idx & 7;
            cp_async16(buf + row * 144 + c8 * 16,
                       qg + (size_t)row * 512 + kk + c8 * 8);
            cp_async16(buf + 64 * 144 + row * 144 + c8 * 16,
                       kg + (size_t)row * 512 + kk + c8 * 8);
        }
    };

    float acc[8][4];
    #pragma unroll
    for (int j = 0; j < 8; ++j)
        #pragma unroll
        for (int r = 0; r < 4; ++r) acc[j][r] = 0.f;

    const int quad = lane >> 3, lr = lane & 7;
    const uint32_t offA = (uint32_t)(w * 16 + (quad & 1) * 8 + lr) * 144 + (quad >> 1) * 16;
    const uint32_t offB = (uint32_t)((quad & 1) * 8 + lr) * 144 + (quad >> 1) * 16;

    load(0); CP_COMMIT();
    for (int c = 0; c < 4; ++c) {
        CP_WAIT0();
        __syncthreads();
        if (c < 3) { load(c + 1); CP_COMMIT(); }
        const uint32_t qs  = s0 + (c & 1) * (2 * 64 * 144);
        const uint32_t ks_ = qs + 64 * 144;
        #pragma unroll
        for (int kh = 0; kh < 4; ++kh) {
            uint32_t a[4], bq[4][4];
            ldsm4(a, qs + offA + kh * 32);
            #pragma unroll
            for (int p = 0; p < 4; ++p)
                ldsm4(bq[p], ks_ + offB + p * 16 * 144 + kh * 32);
            #pragma unroll
            for (int p = 0; p < 4; ++p) {
                mma_f16(acc[2 * p],     a[0], a[1], a[2], a[3], bq[p][0], bq[p][2]);
                mma_f16(acc[2 * p + 1], a[0], a[1], a[2], a[3], bq[p][1], bq[p][3]);
            }
        }
    }

    const int g = lane >> 2, t4 = lane & 3;
    float* sp = g_spart + (size_t)(bh * kNCH + ch) * 64 * 64;
    #pragma unroll
    for (int nt = 0; nt < 8; ++nt) {
        const int row = w * 16 + g, col = nt * 8 + t4 * 2;
        sp[row * 64 + col]           = acc[nt][0];
        sp[row * 64 + col + 1]       = acc[nt][1];
        sp[(row + 8) * 64 + col]     = acc[nt][2];
        sp[(row + 8) * 64 + col + 1] = acc[nt][3];
    }
}

// ---------------- softmax ----------------
__global__ __launch_bounds__(256) void softmax_kernel()
{
    int bh = blockIdx.x;
    int dd = blockIdx.y * 8 + (threadIdx.x >> 5);
    int lane = threadIdx.x & 31;
    const float* spb = g_spart + (size_t)bh * kNCH * 64 * 64 + dd * 64;
    float v0 = 0.f, v1 = 0.f;
    #pragma unroll
    for (int p = 0; p < kNCH; ++p) {
        v0 += spb[(size_t)p * 64 * 64 + lane];
        v1 += spb[(size_t)p * 64 * 64 + 32 + lane];
    }
    float m = fmaxf(v0, v1);
    #pragma unroll
    for (int off = 16; off; off >>= 1) m = fmaxf(m, __shfl_xor_sync(0xffffffffu, m, off));
    v0 = expf(v0 - m); v1 = expf(v1 - m);
    float s = v0 + v1;
    #pragma unroll
    for (int off = 16; off; off >>= 1) s += __shfl_xor_sync(0xffffffffu, s, off);
    float inv = 1.f / s;
    __half* at = h_attnw + (size_t)bh * 64 * 64 + dd * 64;
    at[lane]      = __float2half(v0 * inv);
    at[32 + lane] = __float2half(v1 * inv);
}

// ---------------- AV ----------------
__global__ __launch_bounds__(128) void attn_av_tc()
{
    const int bh = blockIdx.y, b = bh >> 2, h = bh & 3;
    const int n0 = blockIdx.x * 128;
    __shared__ __align__(16) __half sV[128 * 72];
    __shared__ __align__(16) __half sA[64 * 72];
    const int tid = threadIdx.x, lane = tid & 31, w = tid >> 5;
    const uint32_t vb = smem_u32(sV), ab = smem_u32(sA);

    #pragma unroll
    for (int j = 0; j < 8; ++j) {
        int idx = tid + j * 128;
        int row = idx >> 3, c8 = idx & 7;
        cp_async16(vb + row * 144 + c8 * 16,
                   h_v + ((size_t)(b * 4096 + n0 + row)) * 256 + h * 64 + c8 * 8);
    }
    #pragma unroll
    for (int j = 0; j < 4; ++j) {
        int idx = tid + j * 128;
        int row = idx >> 3, c8 = idx & 7;
        cp_async16(ab + row * 144 + c8 * 16,
                   h_attnw + (size_t)bh * 4096 + row * 64 + c8 * 8);
    }
    CP_COMMIT();
    CP_WAIT0();
    __syncthreads();

    const int quad = lane >> 3, lr = lane & 7;
    const uint32_t offA = (uint32_t)(w * 32 + (quad & 1) * 8 + lr) * 144 + (quad >> 1) * 16;
    const uint32_t offB = (uint32_t)((quad & 1) * 8 + lr) * 144 + (quad >> 1) * 16;

    float acc[2][8][4];
    #pragma unroll
    for (int i = 0; i < 2; ++i)
        #pragma unroll
        for (int j = 0; j < 8; ++j)
            #pragma unroll
            for (int r = 0; r < 4; ++r) acc[i][j][r] = 0.f;

    #pragma unroll
    for (int ks = 0; ks < 4; ++ks) {
        uint32_t a[2][4], bq[4][4];
        ldsm4(a[0], vb + offA + ks * 32);
        ldsm4(a[1], vb + offA + 16 * 144 + ks * 32);
        #pragma unroll
        for (int p = 0; p < 4; ++p)
            ldsm4(bq[p], ab + offB + p * 16 * 144 + ks * 32);
        #pragma unroll
        for (int mt = 0; mt < 2; ++mt)
            #pragma unroll
            for (int p = 0; p < 4; ++p) {
                mma_f16(acc[mt][2 * p],     a[mt][0], a[mt][1], a[mt][2], a[mt][3],
                        bq[p][0], bq[p][2]);
                mma_f16(acc[mt][2 * p + 1], a[mt][0], a[mt][1], a[mt][2], a[mt][3],
                        bq[p][1], bq[p][3]);
            }
    }

    const int g = lane >> 2, t4 = lane & 3;
    #pragma unroll
    for (int mt = 0; mt < 2; ++mt) {
        #pragma unroll
        for (int nt = 0; nt < 8; ++nt) {
            const int n1 = n0 + w * 32 + mt * 16 + g;
            const int d  = nt * 8 + t4 * 2;
            __half* yp = h_attnout + ((size_t)(b * 4096 + n1)) * 256 + h * 64 + d;
            *(__half2*)yp = __floats2half2_rn(acc[mt][nt][0], acc[mt][nt][1]);
            *(__half2*)(yp + 8 * 256) = __floats2half2_rn(acc[mt][nt][2], acc[mt][nt][3]);
        }
    }
}

// ---------------- launch ----------------
extern "C" void kernel_launch(void* const* d_in, const int* in_sizes, int n_in,
                              void* d_out, int out_size)
{
    const float* x      = (const float*)d_in[0];
    const float* w_qkv  = (const float*)d_in[1];
    const float* b_qkv  = (const float*)d_in[2];
    const float* w_proj = (const float*)d_in[3];
    const float* b_proj = (const float*)d_in[4];
    const float* w_ffn1 = (const float*)d_in[5];
    const float* b_ffn1 = (const float*)d_in[6];
    const float* w_ffn2 = (const float*)d_in[7];
    const float* b_ffn2 = (const float*)d_in[8];
    const float* g1     = (const float*)d_in[9];
    const float* be1    = (const float*)d_in[10];
    const float* g2     = (const float*)d_in[11];
    const float* be2    = (const float*)d_in[12];
    float* out = (float*)d_out;

    void *p_xln, *p_v, *p_attnout, *p_ln2, *p_ffh, *p_w;
    cudaGetSymbolAddress(&p_xln, h_xln);
    cudaGetSymbolAddress(&p_v, h_v);
    cudaGetSymbolAddress(&p_attnout, h_attnout);
    cudaGetSymbolAddress(&p_ln2, h_ln2);
    cudaGetSymbolAddress(&p_ffh, h_ffh);
    cudaGetSymbolAddress(&p_w, h_w);
    const __half* hw = (const __half*)p_w;

    cudaFuncSetAttribute(gemm_h<0>, cudaFuncAttributeMaxDynamicSharedMemorySize, SMEM_DYN);
    cudaFuncSetAttribute(gemm_h<1>, cudaFuncAttributeMaxDynamicSharedMemorySize, SMEM_DYN);
    cudaFuncSetAttribute(gemm_h<2>, cudaFuncAttributeMaxDynamicSharedMemorySize, SMEM_DYN);
    cudaFuncSetAttribute(gemm_h<3>, cudaFuncAttributeMaxDynamicSharedMemorySize, SMEM_DYN);
    cudaFuncSetAttribute(gemm_h<4>, cudaFuncAttributeMaxDynamicSharedMemorySize, SMEM_DYN);

    // one-time side stream + events (resources reused; enqueued work identical per call)
    static cudaStream_t s2 = [] { cudaStream_t s; cudaStreamCreateWithFlags(&s, cudaStreamNonBlocking); return s; }();
    static cudaEvent_t evA = [] { cudaEvent_t e; cudaEventCreateWithFlags(&e, cudaEventDisableTiming); return e; }();
    static cudaEvent_t evB = [] { cudaEvent_t e; cudaEventCreateWithFlags(&e, cudaEventDisableTiming); return e; }();
    static cudaEvent_t evC = [] { cudaEvent_t e; cudaEventCreateWithFlags(&e, cudaEventDisableTiming); return e; }();
    static cudaEvent_t evD = [] { cudaEvent_t e; cudaEventCreateWithFlags(&e, cudaEventDisableTiming); return e; }();

    const int M = kB * kN;  // 32768
    cudaStream_t s0 = 0;

    // fork: convw on s2, ln1 on s0
    cudaEventRecord(evA, s0);
    cudaStreamWaitEvent(s2, evA, 0);
    convw_kernel<<<(OW_TOT + 255) / 256, 256, 0, s2>>>(w_qkv, w_proj, w_ffn1, w_ffn2);
    cudaEventRecord(evB, s2);

    ln1_kernel<<<dim3(kN / 32, kB), 256, 0, s0>>>(x, g1, be1);

    // QKV q/k (needs ln1 + convw)
    cudaStreamWaitEvent(s0, evB, 0);
    gemm_h<3><<<dim3(4, M / 128), 256, SMEM_DYN, s0>>>(
        (const __half*)p_xln, hw + OW_QKV, b_qkv, nullptr, nullptr, nullptr, nullptr, kC, kC3);
    cudaEventRecord(evC, s0);

    // QKV v on s2, concurrent with attn_s + softmax on s0
    cudaStreamWaitEvent(s2, evC, 0);
    gemm_h<0><<<dim3(2, M / 128), 256, SMEM_DYN, s2>>>(
        (const __half*)p_xln, hw + OW_QKV + 512 * kC, b_qkv + 512, p_v,
        nullptr, nullptr, nullptr, kC, kC);
    cudaEventRecord(evD, s2);

    attn_s_tc<<<dim3(kBH, kNCH), 128, 0, s0>>>();
    softmax_kernel<<<dim3(kBH, 8), 256, 0, s0>>>();

    // AV needs softmax (s0 order) + h_v (evD)
    cudaStreamWaitEvent(s0, evD, 0);
    attn_av_tc<<<dim3(kN / 128, kBH), 128, 0, s0>>>();

    // proj + fused LN2 -> h_ln2
    gemm_h<4><<<dim3(1, M / 128), 256, SMEM_DYN, s0>>>(
        (const __half*)p_attnout, hw + OW_PROJ, b_proj, p_ln2, nullptr, g2, be2, kC, kC);

    gemm_h<1><<<dim3(kFFN / 128, M / 128), 256, SMEM_DYN, s0>>>(
        (const __half*)p_ln2, hw + OW_FFN1, b_ffn1, p_ffh, nullptr, nullptr, nullptr, kC, kFFN);

    gemm_h<2><<<dim3(kC / 128, M / 128), 256, SMEM_DYN, s0>>>(
        (const __half*)p_ffh, hw + OW_FFN2, b_ffn2, out, x, nullptr, nullptr, kFFN, kC);
}

// round 14
// speedup vs baseline: 1.0482x; 1.0271x over previous
#include <cuda_runtime.h>
#include <cuda_fp16.h>
#include <cstdint>

// ---------------- problem constants ----------------
namespace {
constexpr int kB   = 8;
constexpr int kC   = 256;
constexpr int kN   = 4096;
constexpr int kC3  = 768;
constexpr int kFFN = 2048;
constexpr int kBH  = 32;
constexpr int kNCH = 16;     // 16 split-K CTAs per bh; pairs share one 512-n chunk

constexpr int ROWB   = 144;
constexpr int TILEB  = 128 * ROWB;
constexpr int STAGEB = 2 * TILEB;
constexpr int NSTG   = 3;
constexpr uint32_t SMEM_DYN = STAGEB * NSTG; // 110592 (2 CTAs/SM)

constexpr int OW_QKV  = 0;
constexpr int OW_PROJ = OW_QKV + kC3 * kC;
constexpr int OW_FFN1 = OW_PROJ + kC * kC;
constexpr int OW_FFN2 = OW_FFN1 + kFFN * kC;
constexpr int OW_TOT  = OW_FFN2 + kC * kFFN;
}

// ---------------- scratch ----------------
__device__ __half h_xln[kB * kN * kC];
// chunked q/k layout: [blk(64)][ch(8)][d(64)][nl(512)], blk=(qk*8+b)*4+h
__device__ __half h_qkT[4096 * 4096];
__device__ __half h_v[kB * kN * kC];
__device__ float  g_spart[kBH * kNCH * 64 * 64];
__device__ __half h_attnw[kBH * 64 * 64];
__device__ __half h_attnout[kB * kN * kC];
__device__ __half h_proj[kB * kN * kC];
__device__ __half h_ln2[kB * kN * kC];
__device__ __half h_ffh[kB * kN * kFFN];
__device__ __half h_w[OW_TOT];

// ---------------- helpers ----------------
__device__ __forceinline__ uint32_t smem_u32(const void* p) {
    uint32_t a;
    asm("{ .reg .u64 t; cvta.to.shared.u64 t, %1; cvt.u32.u64 %0, t; }" : "=r"(a) : "l"(p));
    return a;
}
__device__ __forceinline__ void cp_async16(uint32_t s, const void* g) {
    asm volatile("cp.async.cg.shared.global [%0], [%1], 16;" :: "r"(s), "l"(g));
}
#define CP_COMMIT() asm volatile("cp.async.commit_group;" ::: "memory")
#define CP_WAIT1()  asm volatile("cp.async.wait_group 1;" ::: "memory")
#define CP_WAIT0()  asm volatile("cp.async.wait_group 0;" ::: "memory")

__device__ __forceinline__ void ldsm4(uint32_t* r, uint32_t a) {
    asm volatile("ldmatrix.sync.aligned.m8n8.x4.shared.b16 {%0,%1,%2,%3}, [%4];"
                 : "=r"(r[0]), "=r"(r[1]), "=r"(r[2]), "=r"(r[3]) : "r"(a));
}
__device__ __forceinline__ void stsm4(uint32_t a, const uint32_t* r) {
    asm volatile("stmatrix.sync.aligned.m8n8.x4.shared.b16 [%0], {%1,%2,%3,%4};"
                 :: "r"(a), "r"(r[0]), "r"(r[1]), "r"(r[2]), "r"(r[3]) : "memory");
}
__device__ __forceinline__ void mma_f16(float* c,
                                        uint32_t a0, uint32_t a1, uint32_t a2, uint32_t a3,
                                        uint32_t b0, uint32_t b1) {
    asm volatile(
        "mma.sync.aligned.m16n8k16.row.col.f32.f16.f16.f32 "
        "{%0,%1,%2,%3}, {%4,%5,%6,%7}, {%8,%9}, {%0,%1,%2,%3};"
        : "+f"(c[0]), "+f"(c[1]), "+f"(c[2]), "+f"(c[3])
        : "r"(a0), "r"(a1), "r"(a2), "r"(a3), "r"(b0), "r"(b1));
}
__device__ __forceinline__ uint32_t pack_h2(float x, float y) {
    __half2 h = __floats2half2_rn(x, y);
    return *(uint32_t*)&h;
}

// ---------------- weight conversion ----------------
__global__ __launch_bounds__(256) void convw_kernel(const float* __restrict__ wqkv,
                                                    const float* __restrict__ wproj,
                                                    const float* __restrict__ wffn1,
                                                    const float* __restrict__ wffn2)
{
    int i = blockIdx.x * 256 + threadIdx.x;
    if (i >= OW_TOT) return;
    float v;
    if (i < OW_PROJ)       v = wqkv[i - OW_QKV];
    else if (i < OW_FFN1)  v = wproj[i - OW_PROJ];
    else if (i < OW_FFN2)  v = wffn1[i - OW_FFN1];
    else                   v = wffn2[i - OW_FFN2];
    h_w[i] = __float2half(v);
}

// ---------------- LN1 ----------------
__global__ __launch_bounds__(256) void ln1_kernel(const float* __restrict__ x,
                                                  const float* __restrict__ g1,
                                                  const float* __restrict__ be1)
{
    __shared__ float s[32][257];
    __shared__ float smu[32], srs[32];
    int b  = blockIdx.y;
    int n0 = blockIdx.x * 32;
    int tid = threadIdx.x;
    const float* xb = x + (size_t)b * kC * kN;
    #pragma unroll
    for (int it = 0; it < 32; ++it) {
        int idx = it * 256 + tid;
        int c = idx >> 5, nn = idx & 31;
        s[nn][c] = xb[(size_t)c * kN + n0 + nn];
    }
    __syncthreads();
    int nn = tid >> 3, g = tid & 7;
    float sum = 0.f, sq = 0.f;
    #pragma unroll
    for (int j = 0; j < 32; ++j) { float v = s[nn][g + j * 8]; sum += v; sq += v * v; }
    sum += __shfl_xor_sync(0xffffffffu, sum, 1, 8);
    sum += __shfl_xor_sync(0xffffffffu, sum, 2, 8);
    sum += __shfl_xor_sync(0xffffffffu, sum, 4, 8);
    sq  += __shfl_xor_sync(0xffffffffu, sq, 1, 8);
    sq  += __shfl_xor_sync(0xffffffffu, sq, 2, 8);
    sq  += __shfl_xor_sync(0xffffffffu, sq, 4, 8);
    if (g == 0) {
        float mu = sum * (1.f / 256.f);
        smu[nn] = mu;
        srs[nn] = rsqrtf(sq * (1.f / 256.f) - mu * mu + 1e-5f);
    }
    __syncthreads();
    float gg = g1[tid], bb = be1[tid];
    __half* yb = h_xln + ((size_t)b * kN + n0) * kC;
    #pragma unroll
    for (int it = 0; it < 32; ++it)
        yb[(size_t)it * kC + tid] = __float2half((s[it][tid] - smu[it]) * srs[it] * gg + bb);
}

// ---------------- fp16 tensor GEMM 128x128x64 ----------------
// MODE 0: fp16 + bias.  MODE 1: fp16 + bias + ReLU.
// MODE 2: fp32 out (B,C,N), bias + residual + transpose.
// MODE 3: QKV q/k -> chunked h_qkT (q scaled 1/8).
// MODE 4: proj + fused LN2.
// m_base: m-tile offset (for m-split pipelined launches).
template <int MODE>
__global__ __launch_bounds__(256, 2) void gemm_h(const __half* __restrict__ A,
                                                 const __half* __restrict__ W,
                                                 const float* __restrict__ bias,
                                                 void* __restrict__ Yv,
                                                 const float* __restrict__ xres,
                                                 const float* __restrict__ gam,
                                                 const float* __restrict__ bet,
                                                 int K, int O, int m_base)
{
    extern __shared__ __align__(16) char smem[];
    const uint32_t sbase = smem_u32(smem);
    const int tid = threadIdx.x;
    const int lane = tid & 31;
    const int wid = tid >> 5;
    const int g  = lane >> 2;
    const int t4 = lane & 3;
    const int wm = wid >> 1;
    const int wn = wid & 1;
    const int m0 = (m_base + blockIdx.y) * 128;
    const int NC = K >> 6;

    const int r_ld = tid >> 3;
    const int c_ld = tid & 7;

    const int quad = lane >> 3, lr = lane & 7;
    const uint32_t offA = (uint32_t)(wm * 32 + (quad & 1) * 8 + lr) * ROWB + (quad >> 1) * 16;
    const uint32_t offB = (uint32_t)(wn * 64 + (quad & 1) * 8 + lr) * ROWB + (quad >> 1) * 16;

    float acc[2][8][4];

    const int n_iters = (MODE == 4) ? 2 : 1;
    int n0 = (MODE == 4) ? 0 : blockIdx.x * 128;

    for (int ni = 0; ni < n_iters; ++ni) {
        if (MODE == 4) n0 = ni * 128;

        #pragma unroll
        for (int i = 0; i < 2; ++i)
            #pragma unroll
            for (int j = 0; j < 8; ++j)
                #pragma unroll
                for (int r = 0; r < 4; ++r) acc[i][j][r] = 0.f;

        auto load_stage = [&](int t) {
            const int bstg = t % NSTG;
            const uint32_t sA = sbase + bstg * STAGEB;
            const uint32_t sB = sA + TILEB;
            const int k0 = t * 64;
            const __half* Ag = A + (size_t)(m0 + r_ld) * K + k0 + c_ld * 8;
            const __half* Wg = W + (size_t)(n0 + r_ld) * K + k0 + c_ld * 8;
            #pragma unroll
            for (int p = 0; p < 4; ++p) {
                cp_async16(sA + (p * 32 + r_ld) * ROWB + c_ld * 16, Ag + (size_t)(p * 32) * K);
                cp_async16(sB + (p * 32 + r_ld) * ROWB + c_ld * 16, Wg + (size_t)(p * 32) * K);
            }
        };

        load_stage(0); CP_COMMIT();
        load_stage(1); CP_COMMIT();

        for (int t = 0; t < NC; ++t) {
            CP_WAIT1();
            __syncthreads();
            if (t + 2 < NC) { load_stage(t + 2); }
            CP_COMMIT();

            const uint32_t fAb = sbase + (t % NSTG) * STAGEB;
            const uint32_t fBb = fAb + TILEB;

            #pragma unroll
            for (int ks = 0; ks < 4; ++ks) {
                uint32_t a[2][4], bq[4][4];
                ldsm4(a[0], fAb + offA + ks * 32);
                ldsm4(a[1], fAb + offA + 16 * ROWB + ks * 32);
                #pragma unroll
                for (int p = 0; p < 4; ++p)
                    ldsm4(bq[p], fBb + offB + p * 16 * ROWB + ks * 32);
                #pragma unroll
                for (int mt = 0; mt < 2; ++mt)
                    #pragma unroll
                    for (int p = 0; p < 4; ++p) {
                        mma_f16(acc[mt][2 * p],     a[mt][0], a[mt][1], a[mt][2], a[mt][3],
                                bq[p][0], bq[p][2]);
                        mma_f16(acc[mt][2 * p + 1], a[mt][0], a[mt][1], a[mt][2], a[mt][3],
                                bq[p][1], bq[p][3]);
                    }
            }
        }
        CP_WAIT0();
        __syncthreads();

        if (MODE == 4 && ni == 0) {
            const uint32_t stg_b = sbase;
            float2 bv[8];
            #pragma unroll
            for (int nt = 0; nt < 8; ++nt)
                bv[nt] = *(const float2*)(bias + n0 + wn * 64 + nt * 8 + t4 * 2);
            const int q2 = lane >> 3, lr2 = lane & 7;
            #pragma unroll
            for (int mt = 0; mt < 2; ++mt) {
                #pragma unroll
                for (int np = 0; np < 4; ++np) {
                    const int e0 = 2 * np, e1 = 2 * np + 1;
                    uint32_t r[4] = {
                        pack_h2(acc[mt][e0][0] + bv[e0].x, acc[mt][e0][1] + bv[e0].y),
                        pack_h2(acc[mt][e0][2] + bv[e0].x, acc[mt][e0][3] + bv[e0].y),
                        pack_h2(acc[mt][e1][0] + bv[e1].x, acc[mt][e1][1] + bv[e1].y),
                        pack_h2(acc[mt][e1][2] + bv[e1].x, acc[mt][e1][3] + bv[e1].y) };
                    const uint32_t ad = stg_b
                        + (uint32_t)(wm * 32 + mt * 16 + (q2 & 1) * 8 + lr2) * 272
                        + (uint32_t)(wn * 64 + np * 16 + (q2 >> 1) * 8) * 2;
                    stsm4(ad, r);
                }
            }
            __syncthreads();
            const __half* S = (const __half*)smem;
            #pragma unroll
            for (int it = 0; it < 8; ++it) {
                const int id = tid + it * 256;
                const int row = id >> 4, seg = id & 15;
                *(uint4*)(h_proj + (size_t)(m0 + row) * 256 + seg * 8) =
                    *(const uint4*)(S + row * 136 + seg * 8);
            }
            __syncthreads();
        }
    }

    if (MODE == 0 || MODE == 1) {
        const uint32_t stg_b = sbase;
        float2 bv[8];
        #pragma unroll
        for (int nt = 0; nt < 8; ++nt)
            bv[nt] = *(const float2*)(bias + n0 + wn * 64 + nt * 8 + t4 * 2);
        const int q2 = lane >> 3, lr2 = lane & 7;
        #pragma unroll
        for (int mt = 0; mt < 2; ++mt) {
            #pragma unroll
            for (int np = 0; np < 4; ++np) {
                const int e0 = 2 * np, e1 = 2 * np + 1;
                float v0 = acc[mt][e0][0] + bv[e0].x, v1 = acc[mt][e0][1] + bv[e0].y;
                float v2 = acc[mt][e0][2] + bv[e0].x, v3 = acc[mt][e0][3] + bv[e0].y;
                float w0 = acc[mt][e1][0] + bv[e1].x, w1 = acc[mt][e1][1] + bv[e1].y;
                float w2 = acc[mt][e1][2] + bv[e1].x, w3 = acc[mt][e1][3] + bv[e1].y;
                if (MODE == 1) {
                    v0 = fmaxf(v0, 0.f); v1 = fmaxf(v1, 0.f);
                    v2 = fmaxf(v2, 0.f); v3 = fmaxf(v3, 0.f);
                    w0 = fmaxf(w0, 0.f); w1 = fmaxf(w1, 0.f);
                    w2 = fmaxf(w2, 0.f); w3 = fmaxf(w3, 0.f);
                }
                uint32_t r[4] = { pack_h2(v0, v1), pack_h2(v2, v3),
                                  pack_h2(w0, w1), pack_h2(w2, w3) };
                const uint32_t ad = stg_b
                    + (uint32_t)(wm * 32 + mt * 16 + (q2 & 1) * 8 + lr2) * 272
                    + (uint32_t)(wn * 64 + np * 16 + (q2 >> 1) * 8) * 2;
                stsm4(ad, r);
            }
        }
        __syncthreads();
        const __half* S = (const __half*)smem;
        __half* Y = (__half*)Yv;
        #pragma unroll
        for (int it = 0; it < 8; ++it) {
            const int id = tid + it * 256;
            const int row = id >> 4, seg = id & 15;
            *(uint4*)(Y + (size_t)(m0 + row) * O + n0 + seg * 8) =
                *(const uint4*)(S + row * 136 + seg * 8);
        }
        return;
    }

    if (MODE == 4) {
        const uint32_t stg_b = sbase;
        float2 bv[8];
        #pragma unroll
        for (int nt = 0; nt < 8; ++nt)
            bv[nt] = *(const float2*)(bias + 128 + wn * 64 + nt * 8 + t4 * 2);
        const int q2 = lane >> 3, lr2 = lane & 7;
        #pragma unroll
        for (int mt = 0; mt < 2; ++mt) {
            #pragma unroll
            for (int np = 0; np < 4; ++np) {
                const int e0 = 2 * np, e1 = 2 * np + 1;
                uint32_t r[4] = {
                    pack_h2(acc[mt][e0][0] + bv[e0].x, acc[mt][e0][1] + bv[e0].y),
                    pack_h2(acc[mt][e0][2] + bv[e0].x, acc[mt][e0][3] + bv[e0].y),
                    pack_h2(acc[mt][e1][0] + bv[e1].x, acc[mt][e1][1] + bv[e1].y),
                    pack_h2(acc[mt][e1][2] + bv[e1].x, acc[mt][e1][3] + bv[e1].y) };
                const uint32_t ad = stg_b
                    + (uint32_t)(wm * 32 + mt * 16 + (q2 & 1) * 8 + lr2) * 272
                    + (uint32_t)(wn * 64 + np * 16 + (q2 >> 1) * 8) * 2;
                stsm4(ad, r);
            }
        }
        float* sgb = (float*)(smem + 36864);
        if (tid < 256) { sgb[tid] = gam[tid]; sgb[256 + tid] = bet[tid]; }
        __syncthreads();

        const int row = tid >> 1, half = tid & 1;
        const uint4* src = half
            ? (const uint4*)((const __half*)smem + row * 136)
            : (const uint4*)(h_proj + (size_t)(m0 + row) * 256);
        float sum = 0.f, sq = 0.f;
        #pragma unroll
        for (int i = 0; i < 16; ++i) {
            uint4 u = src[i];
            const __half2* hh = (const __half2*)&u;
            #pragma unroll
            for (int q = 0; q < 4; ++q) {
                float2 f = __half22float2(hh[q]);
                sum += f.x + f.y;
                sq  += f.x * f.x + f.y * f.y;
            }
        }
        sum += __shfl_xor_sync(0xffffffffu, sum, 1);
        sq  += __shfl_xor_sync(0xffffffffu, sq, 1);
        const float mu = sum * (1.f / 256.f);
        const float rs = rsqrtf(sq * (1.f / 256.f) - mu * mu + 1e-5f);

        __half* Y = (__half*)Yv;
        __half* dst = Y + (size_t)(m0 + row) * 256 + half * 128;
        const float* gp = sgb + half * 128;
        const float* bp = sgb + 256 + half * 128;
        #pragma unroll
        for (int i = 0; i < 16; ++i) {
            uint4 u = src[i];
            const __half2* hh = (const __half2*)&u;
            __half2 o[4];
            #pragma unroll
            for (int q = 0; q < 4; ++q) {
                float2 f = __half22float2(hh[q]);
                const int c = i * 8 + q * 2;
                o[q] = __floats2half2_rn((f.x - mu) * rs * gp[c]     + bp[c],
                                         (f.y - mu) * rs * gp[c + 1] + bp[c + 1]);
            }
            *(uint4*)(dst + i * 8) = *(uint4*)o;
        }
        return;
    }

    float* stg = (float*)smem;
    #pragma unroll
    for (int mt = 0; mt < 2; ++mt) {
        #pragma unroll
        for (int nt = 0; nt < 8; ++nt) {
            const int row = wm * 32 + mt * 16 + g;
            const int col = wn * 64 + nt * 8 + t4 * 2;
            stg[row * 133 + col]           = acc[mt][nt][0];
            stg[row * 133 + col + 1]       = acc[mt][nt][1];
            stg[(row + 8) * 133 + col]     = acc[mt][nt][2];
            stg[(row + 8) * 133 + col + 1] = acc[mt][nt][3];
        }
    }
    __syncthreads();

    if (MODE == 2) {
        float* Y = (float*)Yv;
        const int bidx = m0 >> 12;
        const int npix = m0 & 4095;
        #pragma unroll
        for (int ci = 0; ci < 16; ++ci) {
            const int c = wid * 16 + ci;
            const int cg = n0 + c;
            const float bv = bias[cg];
            const size_t base = (((size_t)(bidx * 256 + cg)) << 12) + npix;
            #pragma unroll
            for (int i = 0; i < 4; ++i) {
                const int m = lane + 32 * i;
                Y[base + m] = stg[m * 133 + c] + bv + xres[base + m];
            }
        }
    } else {  // MODE 3 (q/k only; n0 < 512 by grid construction)
        const int bidx = m0 >> 12;
        const int npix = m0 & 4095;
        const int ch   = npix >> 9;
        const int nl   = npix & 511;
        #pragma unroll
        for (int ci = 0; ci < 16; ++ci) {
            const int c  = wid * 16 + ci;
            const int cg = n0 + c;
            const int qk = cg >> 8;
            const int hh = (cg >> 6) & 3;
            const int d  = cg & 63;
            const float sc = qk ? 1.f : 0.125f;
            const float bv = bias[cg];
            const int blk = (qk * 8 + bidx) * 4 + hh;
            __half* rp = h_qkT + ((size_t)((blk * 8 + ch) * 64 + d)) * 512
                       + nl + lane * 4;
            float v0 = (stg[(lane * 4 + 0) * 133 + c] + bv) * sc;
            float v1 = (stg[(lane * 4 + 1) * 133 + c] + bv) * sc;
            float v2 = (stg[(lane * 4 + 2) * 133 + c] + bv) * sc;
            float v3 = (stg[(lane * 4 + 3) * 133 + c] + bv) * sc;
            __half2 o[2] = { __floats2half2_rn(v0, v1), __floats2half2_rn(v2, v3) };
            *(uint2*)rp = *(uint2*)o;
        }
    }
}

// ---------------- attention S (split-K x16; two CTAs per 512-chunk) ----------------
__global__ __launch_bounds__(128) void attn_s_tc()
{
    const int bh = blockIdx.x, ch = blockIdx.y;    // ch 0..15
    const int chunk = ch >> 1, halfc = ch & 1;     // 512-chunk, 256-col half
    const int b = bh >> 2, h = bh & 3;
    __shared__ __align__(16) char sbuf[2][2 * 64 * 144];
    const int tid = threadIdx.x, lane = tid & 31, w = tid >> 5;
    const uint32_t s0 = smem_u32(sbuf);
    const __half* qg = h_qkT + ((size_t)(((b * 4 + h) * 8 + chunk) * 64)) * 512 + halfc * 256;
    const __half* kg = h_qkT + ((size_t)(((32 + b * 4 + h) * 8 + chunk) * 64)) * 512 + halfc * 256;

    auto load = [&](int c) {
        const uint32_t buf = s0 + (c & 1) * (2 * 64 * 144);
        const int kk = c * 64;
        #pragma unroll
        for (int j = 0; j < 4; ++j) {
            int idx = j * 128 + tid;
            int row = idx >> 3, c8 = idx & 7;
            cp_async16(buf + row * 144 + c8 * 16,
                       qg + (size_t)row * 512 + kk + c8 * 8);
            cp_async16(buf + 64 * 144 + row * 144 + c8 * 16,
                       kg + (size_t)row * 512 + kk + c8 * 8);
        }
    };

    float acc[8][4];
    #pragma unroll
    for (int j = 0; j < 8; ++j)
        #pragma unroll
        for (int r = 0; r < 4; ++r) acc[j][r] = 0.f;

    const int quad = lane >> 3, lr = lane & 7;
    const uint32_t offA = (uint32_t)(w * 16 + (quad & 1) * 8 + lr) * 144 + (quad >> 1) * 16;
    const uint32_t offB = (uint32_t)((quad & 1) * 8 + lr) * 144 + (quad >> 1) * 16;

    load(0); CP_COMMIT();
    for (int c = 0; c < 4; ++c) {
        CP_WAIT0();
        __syncthreads();
        if (c < 3) { load(c + 1); CP_COMMIT(); }
        const uint32_t qs  = s0 + (c & 1) * (2 * 64 * 144);
        const uint32_t ks_ = qs + 64 * 144;
        #pragma unroll
        for (int kh = 0; kh < 4; ++kh) {
            uint32_t a[4], bq[4][4];
            ldsm4(a, qs + offA + kh * 32);
            #pragma unroll
            for (int p = 0; p < 4; ++p)
                ldsm4(bq[p], ks_ + offB + p * 16 * 144 + kh * 32);
            #pragma unroll
            for (int p = 0; p < 4; ++p) {
                mma_f16(acc[2 * p],     a[0], a[1], a[2], a[3], bq[p][0], bq[p][2]);
                mma_f16(acc[2 * p + 1], a[0], a[1], a[2], a[3], bq[p][1], bq[p][3]);
            }
        }
    }

    const int g = lane >> 2, t4 = lane & 3;
    float* sp = g_spart + (size_t)(bh * kNCH + ch) * 64 * 64;
    #pragma unroll
    for (int nt = 0; nt < 8; ++nt) {
        const int row = w * 16 + g, col = nt * 8 + t4 * 2;
        sp[row * 64 + col]           = acc[nt][0];
        sp[row * 64 + col + 1]       = acc[nt][1];
        sp[(row + 8) * 64 + col]     = acc[nt][2];
        sp[(row + 8) * 64 + col + 1] = acc[nt][3];
    }
}

// ---------------- softmax ----------------
__global__ __launch_bounds__(256) void softmax_kernel()
{
    int bh = blockIdx.x;
    int dd = blockIdx.y * 8 + (threadIdx.x >> 5);
    int lane = threadIdx.x & 31;
    const float* spb = g_spart + (size_t)bh * kNCH * 64 * 64 + dd * 64;
    float v0 = 0.f, v1 = 0.f;
    #pragma unroll
    for (int p = 0; p < kNCH; ++p) {
        v0 += spb[(size_t)p * 64 * 64 + lane];
        v1 += spb[(size_t)p * 64 * 64 + 32 + lane];
    }
    float m = fmaxf(v0, v1);
    #pragma unroll
    for (int off = 16; off; off >>= 1) m = fmaxf(m, __shfl_xor_sync(0xffffffffu, m, off));
    v0 = expf(v0 - m); v1 = expf(v1 - m);
    float s = v0 + v1;
    #pragma unroll
    for (int off = 16; off; off >>= 1) s += __shfl_xor_sync(0xffffffffu, s, off);
    float inv = 1.f / s;
    __half* at = h_attnw + (size_t)bh * 64 * 64 + dd * 64;
    at[lane]      = __float2half(v0 * inv);
    at[32 + lane] = __float2half(v1 * inv);
}

// ---------------- AV ----------------
__global__ __launch_bounds__(128) void attn_av_tc()
{
    const int bh = blockIdx.y, b = bh >> 2, h = bh & 3;
    const int n0 = blockIdx.x * 128;
    __shared__ __align__(16) __half sV[128 * 72];
    __shared__ __align__(16) __half sA[64 * 72];
    const int tid = threadIdx.x, lane = tid & 31, w = tid >> 5;
    const uint32_t vb = smem_u32(sV), ab = smem_u32(sA);

    #pragma unroll
    for (int j = 0; j < 8; ++j) {
        int idx = tid + j * 128;
        int row = idx >> 3, c8 = idx & 7;
        cp_async16(vb + row * 144 + c8 * 16,
                   h_v + ((size_t)(b * 4096 + n0 + row)) * 256 + h * 64 + c8 * 8);
    }
    #pragma unroll
    for (int j = 0; j < 4; ++j) {
        int idx = tid + j * 128;
        int row = idx >> 3, c8 = idx & 7;
        cp_async16(ab + row * 144 + c8 * 16,
                   h_attnw + (size_t)bh * 4096 + row * 64 + c8 * 8);
    }
    CP_COMMIT();
    CP_WAIT0();
    __syncthreads();

    const int quad = lane >> 3, lr = lane & 7;
    const uint32_t offA = (uint32_t)(w * 32 + (quad & 1) * 8 + lr) * 144 + (quad >> 1) * 16;
    const uint32_t offB = (uint32_t)((quad & 1) * 8 + lr) * 144 + (quad >> 1) * 16;

    float acc[2][8][4];
    #pragma unroll
    for (int i = 0; i < 2; ++i)
        #pragma unroll
        for (int j = 0; j < 8; ++j)
            #pragma unroll
            for (int r = 0; r < 4; ++r) acc[i][j][r] = 0.f;

    #pragma unroll
    for (int ks = 0; ks < 4; ++ks) {
        uint32_t a[2][4], bq[4][4];
        ldsm4(a[0], vb + offA + ks * 32);
        ldsm4(a[1], vb + offA + 16 * 144 + ks * 32);
        #pragma unroll
        for (int p = 0; p < 4; ++p)
            ldsm4(bq[p], ab + offB + p * 16 * 144 + ks * 32);
        #pragma unroll
        for (int mt = 0; mt < 2; ++mt)
            #pragma unroll
            for (int p = 0; p < 4; ++p) {
                mma_f16(acc[mt][2 * p],     a[mt][0], a[mt][1], a[mt][2], a[mt][3],
                        bq[p][0], bq[p][2]);
                mma_f16(acc[mt][2 * p + 1], a[mt][0], a[mt][1], a[mt][2], a[mt][3],
                        bq[p][1], bq[p][3]);
            }
    }

    const int g = lane >> 2, t4 = lane & 3;
    #pragma unroll
    for (int mt = 0; mt < 2; ++mt) {
        #pragma unroll
        for (int nt = 0; nt < 8; ++nt) {
            const int n1 = n0 + w * 32 + mt * 16 + g;
            const int d  = nt * 8 + t4 * 2;
            __half* yp = h_attnout + ((size_t)(b * 4096 + n1)) * 256 + h * 64 + d;
            *(__half2*)yp = __floats2half2_rn(acc[mt][nt][0], acc[mt][nt][1]);
            *(__half2*)(yp + 8 * 256) = __floats2half2_rn(acc[mt][nt][2], acc[mt][nt][3]);
        }
    }
}

// ---------------- launch ----------------
extern "C" void kernel_launch(void* const* d_in, const int* in_sizes, int n_in,
                              void* d_out, int out_size)
{
    const float* x      = (const float*)d_in[0];
    const float* w_qkv  = (const float*)d_in[1];
    const float* b_qkv  = (const float*)d_in[2];
    const float* w_proj = (const float*)d_in[3];
    const float* b_proj = (const float*)d_in[4];
    const float* w_ffn1 = (const float*)d_in[5];
    const float* b_ffn1 = (const float*)d_in[6];
    const float* w_ffn2 = (const float*)d_in[7];
    const float* b_ffn2 = (const float*)d_in[8];
    const float* g1     = (const float*)d_in[9];
    const float* be1    = (const float*)d_in[10];
    const float* g2     = (const float*)d_in[11];
    const float* be2    = (const float*)d_in[12];
    float* out = (float*)d_out;

    void *p_xln, *p_v, *p_attnout, *p_ln2, *p_ffh, *p_w;
    cudaGetSymbolAddress(&p_xln, h_xln);
    cudaGetSymbolAddress(&p_v, h_v);
    cudaGetSymbolAddress(&p_attnout, h_attnout);
    cudaGetSymbolAddress(&p_ln2, h_ln2);
    cudaGetSymbolAddress(&p_ffh, h_ffh);
    cudaGetSymbolAddress(&p_w, h_w);
    const __half* hw = (const __half*)p_w;

    cudaFuncSetAttribute(gemm_h<0>, cudaFuncAttributeMaxDynamicSharedMemorySize, SMEM_DYN);
    cudaFuncSetAttribute(gemm_h<1>, cudaFuncAttributeMaxDynamicSharedMemorySize, SMEM_DYN);
    cudaFuncSetAttribute(gemm_h<2>, cudaFuncAttributeMaxDynamicSharedMemorySize, SMEM_DYN);
    cudaFuncSetAttribute(gemm_h<3>, cudaFuncAttributeMaxDynamicSharedMemorySize, SMEM_DYN);
    cudaFuncSetAttribute(gemm_h<4>, cudaFuncAttributeMaxDynamicSharedMemorySize, SMEM_DYN);

    static cudaStream_t s2 = [] { cudaStream_t s; cudaStreamCreateWithFlags(&s, cudaStreamNonBlocking); return s; }();
    static cudaEvent_t evA = [] { cudaEvent_t e; cudaEventCreateWithFlags(&e, cudaEventDisableTiming); return e; }();
    static cudaEvent_t evB = [] { cudaEvent_t e; cudaEventCreateWithFlags(&e, cudaEventDisableTiming); return e; }();
    static cudaEvent_t evC = [] { cudaEvent_t e; cudaEventCreateWithFlags(&e, cudaEventDisableTiming); return e; }();
    static cudaEvent_t evD = [] { cudaEvent_t e; cudaEventCreateWithFlags(&e, cudaEventDisableTiming); return e; }();
    static cudaEvent_t evE = [] { cudaEvent_t e; cudaEventCreateWithFlags(&e, cudaEventDisableTiming); return e; }();
    static cudaEvent_t evF = [] { cudaEvent_t e; cudaEventCreateWithFlags(&e, cudaEventDisableTiming); return e; }();

    const int M = kB * kN;    // 32768
    const int MT = M / 128;   // 256 m-tiles
    cudaStream_t s0 = 0;

    // fork: convw on s2, ln1 on s0
    cudaEventRecord(evA, s0);
    cudaStreamWaitEvent(s2, evA, 0);
    convw_kernel<<<(OW_TOT + 255) / 256, 256, 0, s2>>>(w_qkv, w_proj, w_ffn1, w_ffn2);
    cudaEventRecord(evB, s2);

    ln1_kernel<<<dim3(kN / 32, kB), 256, 0, s0>>>(x, g1, be1);

    // QKV q/k (needs ln1 + convw)
    cudaStreamWaitEvent(s0, evB, 0);
    gemm_h<3><<<dim3(4, MT), 256, SMEM_DYN, s0>>>(
        (const __half*)p_xln, hw + OW_QKV, b_qkv, nullptr, nullptr, nullptr, nullptr, kC, kC3, 0);
    cudaEventRecord(evC, s0);

    // QKV v on s2, concurrent with attn_s + softmax on s0
    cudaStreamWaitEvent(s2, evC, 0);
    gemm_h<0><<<dim3(2, MT), 256, SMEM_DYN, s2>>>(
        (const __half*)p_xln, hw + OW_QKV + 512 * kC, b_qkv + 512, p_v,
        nullptr, nullptr, nullptr, kC, kC, 0);
    cudaEventRecord(evD, s2);

    attn_s_tc<<<dim3(kBH, kNCH), 128, 0, s0>>>();
    softmax_kernel<<<dim3(kBH, 8), 256, 0, s0>>>();

    // AV needs softmax (s0 order) + h_v (evD)
    cudaStreamWaitEvent(s0, evD, 0);
    attn_av_tc<<<dim3(kN / 128, kBH), 128, 0, s0>>>();

    // proj + fused LN2 -> h_ln2
    gemm_h<4><<<dim3(1, MT), 256, SMEM_DYN, s0>>>(
        (const __half*)p_attnout, hw + OW_PROJ, b_proj, p_ln2, nullptr, g2, be2, kC, kC, 0);

    // FFN1 m-half A
    gemm_h<1><<<dim3(kFFN / 128, MT / 2), 256, SMEM_DYN, s0>>>(
        (const __half*)p_ln2, hw + OW_FFN1, b_ffn1, p_ffh, nullptr, nullptr, nullptr, kC, kFFN, 0);
    cudaEventRecord(evE, s0);

    // FFN2 m-half A on s2, concurrent with FFN1 m-half B on s0
    cudaStreamWaitEvent(s2, evE, 0);
    gemm_h<2><<<dim3(kC / 128, MT / 2), 256, SMEM_DYN, s2>>>(
        (const __half*)p_ffh, hw + OW_FFN2, b_ffn2, out, x, nullptr, nullptr, kFFN, kC, 0);
    cudaEventRecord(evF, s2);

    // FFN1 m-half B
    gemm_h<1><<<dim3(kFFN / 128, MT / 2), 256, SMEM_DYN, s0>>>(
        (const __half*)p_ln2, hw + OW_FFN1, b_ffn1, p_ffh, nullptr, nullptr, nullptr, kC, kFFN, MT / 2);

    // FFN2 m-half B
    gemm_h<2><<<dim3(kC / 128, MT / 2), 256, SMEM_DYN, s0>>>(
        (const __half*)p_ffh, hw + OW_FFN2, b_ffn2, out, x, nullptr, nullptr, kFFN, kC, MT / 2);

    // join s2 branch into s0 so the graph's terminal depends on FFN2_mA too
    cudaStreamWaitEvent(s0, evF, 0);
}

// round 15
// speedup vs baseline: 1.0658x; 1.0168x over previous
#include <cuda_runtime.h>
#include <cuda_fp16.h>
#include <cstdint>

// ---------------- problem constants ----------------
namespace {
constexpr int kB   = 8;
constexpr int kC   = 256;
constexpr int kN   = 4096;
constexpr int kC3  = 768;
constexpr int kFFN = 2048;
constexpr int kBH  = 32;
constexpr int kNCH = 16;     // 16 split-K CTAs per bh; pairs share one 512-n chunk

constexpr int ROWB   = 144;
constexpr int TILEB  = 128 * ROWB;
constexpr int STAGEB = 2 * TILEB;
constexpr int NSTG   = 3;
constexpr uint32_t SMEM_DYN = STAGEB * NSTG; // 110592 (2 CTAs/SM)

constexpr int OW_QKV  = 0;
constexpr int OW_PROJ = OW_QKV + kC3 * kC;
constexpr int OW_FFN1 = OW_PROJ + kC * kC;
constexpr int OW_FFN2 = OW_FFN1 + kFFN * kC;
constexpr int OW_TOT  = OW_FFN2 + kC * kFFN;
}

// ---------------- scratch ----------------
__device__ __half h_xln[kB * kN * kC];
// chunked q/k layout: [blk(64)][ch(8)][d(64)][nl(512)], blk=(qk*8+b)*4+h
__device__ __half h_qkT[4096 * 4096];
__device__ __half h_v[kB * kN * kC];
__device__ float  g_spart[kBH * kNCH * 64 * 64];
__device__ __half h_attnw[kBH * 64 * 64];
__device__ __half h_attnout[kB * kN * kC];
__device__ __half h_proj[kB * kN * kC];
__device__ __half h_ln2[kB * kN * kC];
__device__ __half h_ffh[kB * kN * kFFN];
__device__ __half h_w[OW_TOT];

// ---------------- helpers ----------------
__device__ __forceinline__ uint32_t smem_u32(const void* p) {
    uint32_t a;
    asm("{ .reg .u64 t; cvta.to.shared.u64 t, %1; cvt.u32.u64 %0, t; }" : "=r"(a) : "l"(p));
    return a;
}
__device__ __forceinline__ void cp_async16(uint32_t s, const void* g) {
    asm volatile("cp.async.cg.shared.global [%0], [%1], 16;" :: "r"(s), "l"(g));
}
#define CP_COMMIT() asm volatile("cp.async.commit_group;" ::: "memory")
#define CP_WAIT1()  asm volatile("cp.async.wait_group 1;" ::: "memory")
#define CP_WAIT0()  asm volatile("cp.async.wait_group 0;" ::: "memory")

__device__ __forceinline__ void ldsm4(uint32_t* r, uint32_t a) {
    asm volatile("ldmatrix.sync.aligned.m8n8.x4.shared.b16 {%0,%1,%2,%3}, [%4];"
                 : "=r"(r[0]), "=r"(r[1]), "=r"(r[2]), "=r"(r[3]) : "r"(a));
}
__device__ __forceinline__ void stsm4(uint32_t a, const uint32_t* r) {
    asm volatile("stmatrix.sync.aligned.m8n8.x4.shared.b16 [%0], {%1,%2,%3,%4};"
                 :: "r"(a), "r"(r[0]), "r"(r[1]), "r"(r[2]), "r"(r[3]) : "memory");
}
__device__ __forceinline__ void mma_f16(float* c,
                                        uint32_t a0, uint32_t a1, uint32_t a2, uint32_t a3,
                                        uint32_t b0, uint32_t b1) {
    asm volatile(
        "mma.sync.aligned.m16n8k16.row.col.f32.f16.f16.f32 "
        "{%0,%1,%2,%3}, {%4,%5,%6,%7}, {%8,%9}, {%0,%1,%2,%3};"
        : "+f"(c[0]), "+f"(c[1]), "+f"(c[2]), "+f"(c[3])
        : "r"(a0), "r"(a1), "r"(a2), "r"(a3), "r"(b0), "r"(b1));
}
__device__ __forceinline__ uint32_t pack_h2(float x, float y) {
    __half2 h = __floats2half2_rn(x, y);
    return *(uint32_t*)&h;
}

// ---------------- weight conversion ----------------
__global__ __launch_bounds__(256) void convw_kernel(const float* __restrict__ wqkv,
                                                    const float* __restrict__ wproj,
                                                    const float* __restrict__ wffn1,
                                                    const float* __restrict__ wffn2)
{
    int i = blockIdx.x * 256 + threadIdx.x;
    if (i >= OW_TOT) return;
    float v;
    if (i < OW_PROJ)       v = wqkv[i - OW_QKV];
    else if (i < OW_FFN1)  v = wproj[i - OW_PROJ];
    else if (i < OW_FFN2)  v = wffn1[i - OW_FFN1];
    else                   v = wffn2[i - OW_FFN2];
    h_w[i] = __float2half(v);
}

// ---------------- LN1 ----------------
__global__ __launch_bounds__(256) void ln1_kernel(const float* __restrict__ x,
                                                  const float* __restrict__ g1,
                                                  const float* __restrict__ be1)
{
    __shared__ float s[32][257];
    __shared__ float smu[32], srs[32];
    int b  = blockIdx.y;
    int n0 = blockIdx.x * 32;
    int tid = threadIdx.x;
    const float* xb = x + (size_t)b * kC * kN;
    #pragma unroll
    for (int it = 0; it < 32; ++it) {
        int idx = it * 256 + tid;
        int c = idx >> 5, nn = idx & 31;
        s[nn][c] = xb[(size_t)c * kN + n0 + nn];
    }
    __syncthreads();
    int nn = tid >> 3, g = tid & 7;
    float sum = 0.f, sq = 0.f;
    #pragma unroll
    for (int j = 0; j < 32; ++j) { float v = s[nn][g + j * 8]; sum += v; sq += v * v; }
    sum += __shfl_xor_sync(0xffffffffu, sum, 1, 8);
    sum += __shfl_xor_sync(0xffffffffu, sum, 2, 8);
    sum += __shfl_xor_sync(0xffffffffu, sum, 4, 8);
    sq  += __shfl_xor_sync(0xffffffffu, sq, 1, 8);
    sq  += __shfl_xor_sync(0xffffffffu, sq, 2, 8);
    sq  += __shfl_xor_sync(0xffffffffu, sq, 4, 8);
    if (g == 0) {
        float mu = sum * (1.f / 256.f);
        smu[nn] = mu;
        srs[nn] = rsqrtf(sq * (1.f / 256.f) - mu * mu + 1e-5f);
    }
    __syncthreads();
    float gg = g1[tid], bb = be1[tid];
    __half* yb = h_xln + ((size_t)b * kN + n0) * kC;
    #pragma unroll
    for (int it = 0; it < 32; ++it)
        yb[(size_t)it * kC + tid] = __float2half((s[it][tid] - smu[it]) * srs[it] * gg + bb);
}

// ---------------- fp16 tensor GEMM 128x128x64 ----------------
// MODE 0: fp16 + bias.  MODE 1: fp16 + bias + ReLU.
// MODE 2: fp32 out (B,C,N), bias + residual + transpose.
// MODE 3: QKV q/k -> chunked h_qkT (q scaled 1/8).
// MODE 4: proj + fused LN2.
// m_base: m-tile offset (for m-split pipelined launches).
template <int MODE>
__global__ __launch_bounds__(256, 2) void gemm_h(const __half* __restrict__ A,
                                                 const __half* __restrict__ W,
                                                 const float* __restrict__ bias,
                                                 void* __restrict__ Yv,
                                                 const float* __restrict__ xres,
                                                 const float* __restrict__ gam,
                                                 const float* __restrict__ bet,
                                                 int K, int O, int m_base)
{
    extern __shared__ __align__(16) char smem[];
    const uint32_t sbase = smem_u32(smem);
    const int tid = threadIdx.x;
    const int lane = tid & 31;
    const int wid = tid >> 5;
    const int g  = lane >> 2;
    const int t4 = lane & 3;
    const int wm = wid >> 1;
    const int wn = wid & 1;
    const int m0 = (m_base + blockIdx.y) * 128;
    const int NC = K >> 6;

    const int r_ld = tid >> 3;
    const int c_ld = tid & 7;

    const int quad = lane >> 3, lr = lane & 7;
    const uint32_t offA = (uint32_t)(wm * 32 + (quad & 1) * 8 + lr) * ROWB + (quad >> 1) * 16;
    const uint32_t offB = (uint32_t)(wn * 64 + (quad & 1) * 8 + lr) * ROWB + (quad >> 1) * 16;

    float acc[2][8][4];

    const int n_iters = (MODE == 4) ? 2 : 1;
    int n0 = (MODE == 4) ? 0 : blockIdx.x * 128;

    for (int ni = 0; ni < n_iters; ++ni) {
        if (MODE == 4) n0 = ni * 128;

        #pragma unroll
        for (int i = 0; i < 2; ++i)
            #pragma unroll
            for (int j = 0; j < 8; ++j)
                #pragma unroll
                for (int r = 0; r < 4; ++r) acc[i][j][r] = 0.f;

        auto load_stage = [&](int t) {
            const int bstg = t % NSTG;
            const uint32_t sA = sbase + bstg * STAGEB;
            const uint32_t sB = sA + TILEB;
            const int k0 = t * 64;
            const __half* Ag = A + (size_t)(m0 + r_ld) * K + k0 + c_ld * 8;
            const __half* Wg = W + (size_t)(n0 + r_ld) * K + k0 + c_ld * 8;
            #pragma unroll
            for (int p = 0; p < 4; ++p) {
                cp_async16(sA + (p * 32 + r_ld) * ROWB + c_ld * 16, Ag + (size_t)(p * 32) * K);
                cp_async16(sB + (p * 32 + r_ld) * ROWB + c_ld * 16, Wg + (size_t)(p * 32) * K);
            }
        };

        load_stage(0); CP_COMMIT();
        load_stage(1); CP_COMMIT();

        for (int t = 0; t < NC; ++t) {
            CP_WAIT1();
            __syncthreads();
            if (t + 2 < NC) { load_stage(t + 2); }
            CP_COMMIT();

            const uint32_t fAb = sbase + (t % NSTG) * STAGEB;
            const uint32_t fBb = fAb + TILEB;

            #pragma unroll
            for (int ks = 0; ks < 4; ++ks) {
                uint32_t a[2][4], bq[4][4];
                ldsm4(a[0], fAb + offA + ks * 32);
                ldsm4(a[1], fAb + offA + 16 * ROWB + ks * 32);
                #pragma unroll
                for (int p = 0; p < 4; ++p)
                    ldsm4(bq[p], fBb + offB + p * 16 * ROWB + ks * 32);
                #pragma unroll
                for (int mt = 0; mt < 2; ++mt)
                    #pragma unroll
                    for (int p = 0; p < 4; ++p) {
                        mma_f16(acc[mt][2 * p],     a[mt][0], a[mt][1], a[mt][2], a[mt][3],
                                bq[p][0], bq[p][2]);
                        mma_f16(acc[mt][2 * p + 1], a[mt][0], a[mt][1], a[mt][2], a[mt][3],
                                bq[p][1], bq[p][3]);
                    }
            }
        }
        CP_WAIT0();
        __syncthreads();

        if (MODE == 4 && ni == 0) {
            const uint32_t stg_b = sbase;
            float2 bv[8];
            #pragma unroll
            for (int nt = 0; nt < 8; ++nt)
                bv[nt] = *(const float2*)(bias + n0 + wn * 64 + nt * 8 + t4 * 2);
            const int q2 = lane >> 3, lr2 = lane & 7;
            #pragma unroll
            for (int mt = 0; mt < 2; ++mt) {
                #pragma unroll
                for (int np = 0; np < 4; ++np) {
                    const int e0 = 2 * np, e1 = 2 * np + 1;
                    uint32_t r[4] = {
                        pack_h2(acc[mt][e0][0] + bv[e0].x, acc[mt][e0][1] + bv[e0].y),
                        pack_h2(acc[mt][e0][2] + bv[e0].x, acc[mt][e0][3] + bv[e0].y),
                        pack_h2(acc[mt][e1][0] + bv[e1].x, acc[mt][e1][1] + bv[e1].y),
                        pack_h2(acc[mt][e1][2] + bv[e1].x, acc[mt][e1][3] + bv[e1].y) };
                    const uint32_t ad = stg_b
                        + (uint32_t)(wm * 32 + mt * 16 + (q2 & 1) * 8 + lr2) * 272
                        + (uint32_t)(wn * 64 + np * 16 + (q2 >> 1) * 8) * 2;
                    stsm4(ad, r);
                }
            }
            __syncthreads();
            const __half* S = (const __half*)smem;
            #pragma unroll
            for (int it = 0; it < 8; ++it) {
                const int id = tid + it * 256;
                const int row = id >> 4, seg = id & 15;
                *(uint4*)(h_proj + (size_t)(m0 + row) * 256 + seg * 8) =
                    *(const uint4*)(S + row * 136 + seg * 8);
            }
            __syncthreads();
        }
    }

    if (MODE == 0 || MODE == 1) {
        const uint32_t stg_b = sbase;
        float2 bv[8];
        #pragma unroll
        for (int nt = 0; nt < 8; ++nt)
            bv[nt] = *(const float2*)(bias + n0 + wn * 64 + nt * 8 + t4 * 2);
        const int q2 = lane >> 3, lr2 = lane & 7;
        #pragma unroll
        for (int mt = 0; mt < 2; ++mt) {
            #pragma unroll
            for (int np = 0; np < 4; ++np) {
                const int e0 = 2 * np, e1 = 2 * np + 1;
                float v0 = acc[mt][e0][0] + bv[e0].x, v1 = acc[mt][e0][1] + bv[e0].y;
                float v2 = acc[mt][e0][2] + bv[e0].x, v3 = acc[mt][e0][3] + bv[e0].y;
                float w0 = acc[mt][e1][0] + bv[e1].x, w1 = acc[mt][e1][1] + bv[e1].y;
                float w2 = acc[mt][e1][2] + bv[e1].x, w3 = acc[mt][e1][3] + bv[e1].y;
                if (MODE == 1) {
                    v0 = fmaxf(v0, 0.f); v1 = fmaxf(v1, 0.f);
                    v2 = fmaxf(v2, 0.f); v3 = fmaxf(v3, 0.f);
                    w0 = fmaxf(w0, 0.f); w1 = fmaxf(w1, 0.f);
                    w2 = fmaxf(w2, 0.f); w3 = fmaxf(w3, 0.f);
                }
                uint32_t r[4] = { pack_h2(v0, v1), pack_h2(v2, v3),
                                  pack_h2(w0, w1), pack_h2(w2, w3) };
                const uint32_t ad = stg_b
                    + (uint32_t)(wm * 32 + mt * 16 + (q2 & 1) * 8 + lr2) * 272
                    + (uint32_t)(wn * 64 + np * 16 + (q2 >> 1) * 8) * 2;
                stsm4(ad, r);
            }
        }
        __syncthreads();
        const __half* S = (const __half*)smem;
        __half* Y = (__half*)Yv;
        #pragma unroll
        for (int it = 0; it < 8; ++it) {
            const int id = tid + it * 256;
            const int row = id >> 4, seg = id & 15;
            *(uint4*)(Y + (size_t)(m0 + row) * O + n0 + seg * 8) =
                *(const uint4*)(S + row * 136 + seg * 8);
        }
        return;
    }

    if (MODE == 4) {
        const uint32_t stg_b = sbase;
        float2 bv[8];
        #pragma unroll
        for (int nt = 0; nt < 8; ++nt)
            bv[nt] = *(const float2*)(bias + 128 + wn * 64 + nt * 8 + t4 * 2);
        const int q2 = lane >> 3, lr2 = lane & 7;
        #pragma unroll
        for (int mt = 0; mt < 2; ++mt) {
            #pragma unroll
            for (int np = 0; np < 4; ++np) {
                const int e0 = 2 * np, e1 = 2 * np + 1;
                uint32_t r[4] = {
                    pack_h2(acc[mt][e0][0] + bv[e0].x, acc[mt][e0][1] + bv[e0].y),
                    pack_h2(acc[mt][e0][2] + bv[e0].x, acc[mt][e0][3] + bv[e0].y),
                    pack_h2(acc[mt][e1][0] + bv[e1].x, acc[mt][e1][1] + bv[e1].y),
                    pack_h2(acc[mt][e1][2] + bv[e1].x, acc[mt][e1][3] + bv[e1].y) };
                const uint32_t ad = stg_b
                    + (uint32_t)(wm * 32 + mt * 16 + (q2 & 1) * 8 + lr2) * 272
                    + (uint32_t)(wn * 64 + np * 16 + (q2 >> 1) * 8) * 2;
                stsm4(ad, r);
            }
        }
        float* sgb = (float*)(smem + 36864);
        if (tid < 256) { sgb[tid] = gam[tid]; sgb[256 + tid] = bet[tid]; }
        __syncthreads();

        const int row = tid >> 1, half = tid & 1;
        const uint4* src = half
            ? (const uint4*)((const __half*)smem + row * 136)
            : (const uint4*)(h_proj + (size_t)(m0 + row) * 256);
        float sum = 0.f, sq = 0.f;
        #pragma unroll
        for (int i = 0; i < 16; ++i) {
            uint4 u = src[i];
            const __half2* hh = (const __half2*)&u;
            #pragma unroll
            for (int q = 0; q < 4; ++q) {
                float2 f = __half22float2(hh[q]);
                sum += f.x + f.y;
                sq  += f.x * f.x + f.y * f.y;
            }
        }
        sum += __shfl_xor_sync(0xffffffffu, sum, 1);
        sq  += __shfl_xor_sync(0xffffffffu, sq, 1);
        const float mu = sum * (1.f / 256.f);
        const float rs = rsqrtf(sq * (1.f / 256.f) - mu * mu + 1e-5f);

        __half* Y = (__half*)Yv;
        __half* dst = Y + (size_t)(m0 + row) * 256 + half * 128;
        const float* gp = sgb + half * 128;
        const float* bp = sgb + 256 + half * 128;
        #pragma unroll
        for (int i = 0; i < 16; ++i) {
            uint4 u = src[i];
            const __half2* hh = (const __half2*)&u;
            __half2 o[4];
            #pragma unroll
            for (int q = 0; q < 4; ++q) {
                float2 f = __half22float2(hh[q]);
                const int c = i * 8 + q * 2;
                o[q] = __floats2half2_rn((f.x - mu) * rs * gp[c]     + bp[c],
                                         (f.y - mu) * rs * gp[c + 1] + bp[c + 1]);
            }
            *(uint4*)(dst + i * 8) = *(uint4*)o;
        }
        return;
    }

    float* stg = (float*)smem;
    #pragma unroll
    for (int mt = 0; mt < 2; ++mt) {
        #pragma unroll
        for (int nt = 0; nt < 8; ++nt) {
            const int row = wm * 32 + mt * 16 + g;
            const int col = wn * 64 + nt * 8 + t4 * 2;
            stg[row * 133 + col]           = acc[mt][nt][0];
            stg[row * 133 + col + 1]       = acc[mt][nt][1];
            stg[(row + 8) * 133 + col]     = acc[mt][nt][2];
            stg[(row + 8) * 133 + col + 1] = acc[mt][nt][3];
        }
    }
    __syncthreads();

    if (MODE == 2) {
        float* Y = (float*)Yv;
        const int bidx = m0 >> 12;
        const int npix = m0 & 4095;
        #pragma unroll
        for (int ci = 0; ci < 16; ++ci) {
            const int c = wid * 16 + ci;
            const int cg = n0 + c;
            const float bv = bias[cg];
            const size_t base = (((size_t)(bidx * 256 + cg)) << 12) + npix;
            #pragma unroll
            for (int i = 0; i < 4; ++i) {
                const int m = lane + 32 * i;
                Y[base + m] = stg[m * 133 + c] + bv + xres[base + m];
            }
        }
    } else {  // MODE 3 (q/k only; n0 < 512 by grid construction)
        const int bidx = m0 >> 12;
        const int npix = m0 & 4095;
        const int ch   = npix >> 9;
        const int nl   = npix & 511;
        #pragma unroll
        for (int ci = 0; ci < 16; ++ci) {
            const int c  = wid * 16 + ci;
            const int cg = n0 + c;
            const int qk = cg >> 8;
            const int hh = (cg >> 6) & 3;
            const int d  = cg & 63;
            const float sc = qk ? 1.f : 0.125f;
            const float bv = bias[cg];
            const int blk = (qk * 8 + bidx) * 4 + hh;
            __half* rp = h_qkT + ((size_t)((blk * 8 + ch) * 64 + d)) * 512
                       + nl + lane * 4;
            float v0 = (stg[(lane * 4 + 0) * 133 + c] + bv) * sc;
            float v1 = (stg[(lane * 4 + 1) * 133 + c] + bv) * sc;
            float v2 = (stg[(lane * 4 + 2) * 133 + c] + bv) * sc;
            float v3 = (stg[(lane * 4 + 3) * 133 + c] + bv) * sc;
            __half2 o[2] = { __floats2half2_rn(v0, v1), __floats2half2_rn(v2, v3) };
            *(uint2*)rp = *(uint2*)o;
        }
    }
}

// ---------------- attention S (split-K x16; two CTAs per 512-chunk) ----------------
__global__ __launch_bounds__(128) void attn_s_tc()
{
    const int bh = blockIdx.x, ch = blockIdx.y;    // ch 0..15
    const int chunk = ch >> 1, halfc = ch & 1;     // 512-chunk, 256-col half
    const int b = bh >> 2, h = bh & 3;
    __shared__ __align__(16) char sbuf[2][2 * 64 * 144];
    const int tid = threadIdx.x, lane = tid & 31, w = tid >> 5;
    const uint32_t s0 = smem_u32(sbuf);
    const __half* qg = h_qkT + ((size_t)(((b * 4 + h) * 8 + chunk) * 64)) * 512 + halfc * 256;
    const __half* kg = h_qkT + ((size_t)(((32 + b * 4 + h) * 8 + chunk) * 64)) * 512 + halfc * 256;

    auto load = [&](int c) {
        const uint32_t buf = s0 + (c & 1) * (2 * 64 * 144);
        const int kk = c * 64;
        #pragma unroll
        for (int j = 0; j < 4; ++j) {
            int idx = j * 128 + tid;
            int row = idx >> 3, c8 = idx & 7;
            cp_async16(buf + row * 144 + c8 * 16,
                       qg + (size_t)row * 512 + kk + c8 * 8);
            cp_async16(buf + 64 * 144 + row * 144 + c8 * 16,
                       kg + (size_t)row * 512 + kk + c8 * 8);
        }
    };

    float acc[8][4];
    #pragma unroll
    for (int j = 0; j < 8; ++j)
        #pragma unroll
        for (int r = 0; r < 4; ++r) acc[j][r] = 0.f;

    const int quad = lane >> 3, lr = lane & 7;
    const uint32_t offA = (uint32_t)(w * 16 + (quad & 1) * 8 + lr) * 144 + (quad >> 1) * 16;
    const uint32_t offB = (uint32_t)((quad & 1) * 8 + lr) * 144 + (quad >> 1) * 16;

    load(0); CP_COMMIT();
    for (int c = 0; c < 4; ++c) {
        CP_WAIT0();
        __syncthreads();
        if (c < 3) { load(c + 1); CP_COMMIT(); }
        const uint32_t qs  = s0 + (c & 1) * (2 * 64 * 144);
        const uint32_t ks_ = qs + 64 * 144;
        #pragma unroll
        for (int kh = 0; kh < 4; ++kh) {
            uint32_t a[4], bq[4][4];
            ldsm4(a, qs + offA + kh * 32);
            #pragma unroll
            for (int p = 0; p < 4; ++p)
                ldsm4(bq[p], ks_ + offB + p * 16 * 144 + kh * 32);
            #pragma unroll
            for (int p = 0; p < 4; ++p) {
                mma_f16(acc[2 * p],     a[0], a[1], a[2], a[3], bq[p][0], bq[p][2]);
                mma_f16(acc[2 * p + 1], a[0], a[1], a[2], a[3], bq[p][1], bq[p][3]);
            }
        }
    }

    const int g = lane >> 2, t4 = lane & 3;
    float* sp = g_spart + (size_t)(bh * kNCH + ch) * 64 * 64;
    #pragma unroll
    for (int nt = 0; nt < 8; ++nt) {
        const int row = w * 16 + g, col = nt * 8 + t4 * 2;
        sp[row * 64 + col]           = acc[nt][0];
        sp[row * 64 + col + 1]       = acc[nt][1];
        sp[(row + 8) * 64 + col]     = acc[nt][2];
        sp[(row + 8) * 64 + col + 1] = acc[nt][3];
    }
}

// ---------------- softmax ----------------
__global__ __launch_bounds__(256) void softmax_kernel()
{
    int bh = blockIdx.x;
    int dd = blockIdx.y * 8 + (threadIdx.x >> 5);
    int lane = threadIdx.x & 31;
    const float* spb = g_spart + (size_t)bh * kNCH * 64 * 64 + dd * 64;
    float v0 = 0.f, v1 = 0.f;
    #pragma unroll
    for (int p = 0; p < kNCH; ++p) {
        v0 += spb[(size_t)p * 64 * 64 + lane];
        v1 += spb[(size_t)p * 64 * 64 + 32 + lane];
    }
    float m = fmaxf(v0, v1);
    #pragma unroll
    for (int off = 16; off; off >>= 1) m = fmaxf(m, __shfl_xor_sync(0xffffffffu, m, off));
    v0 = expf(v0 - m); v1 = expf(v1 - m);
    float s = v0 + v1;
    #pragma unroll
    for (int off = 16; off; off >>= 1) s += __shfl_xor_sync(0xffffffffu, s, off);
    float inv = 1.f / s;
    __half* at = h_attnw + (size_t)bh * 64 * 64 + dd * 64;
    at[lane]      = __float2half(v0 * inv);
    at[32 + lane] = __float2half(v1 * inv);
}

// ---------------- AV (bh_base for m-split) ----------------
__global__ __launch_bounds__(128) void attn_av_tc(int bh_base)
{
    const int bh = bh_base + blockIdx.y, b = bh >> 2, h = bh & 3;
    const int n0 = blockIdx.x * 128;
    __shared__ __align__(16) __half sV[128 * 72];
    __shared__ __align__(16) __half sA[64 * 72];
    const int tid = threadIdx.x, lane = tid & 31, w = tid >> 5;
    const uint32_t vb = smem_u32(sV), ab = smem_u32(sA);

    #pragma unroll
    for (int j = 0; j < 8; ++j) {
        int idx = tid + j * 128;
        int row = idx >> 3, c8 = idx & 7;
        cp_async16(vb + row * 144 + c8 * 16,
                   h_v + ((size_t)(b * 4096 + n0 + row)) * 256 + h * 64 + c8 * 8);
    }
    #pragma unroll
    for (int j = 0; j < 4; ++j) {
        int idx = tid + j * 128;
        int row = idx >> 3, c8 = idx & 7;
        cp_async16(ab + row * 144 + c8 * 16,
                   h_attnw + (size_t)bh * 4096 + row * 64 + c8 * 8);
    }
    CP_COMMIT();
    CP_WAIT0();
    __syncthreads();

    const int quad = lane >> 3, lr = lane & 7;
    const uint32_t offA = (uint32_t)(w * 32 + (quad & 1) * 8 + lr) * 144 + (quad >> 1) * 16;
    const uint32_t offB = (uint32_t)((quad & 1) * 8 + lr) * 144 + (quad >> 1) * 16;

    float acc[2][8][4];
    #pragma unroll
    for (int i = 0; i < 2; ++i)
        #pragma unroll
        for (int j = 0; j < 8; ++j)
            #pragma unroll
            for (int r = 0; r < 4; ++r) acc[i][j][r] = 0.f;

    #pragma unroll
    for (int ks = 0; ks < 4; ++ks) {
        uint32_t a[2][4], bq[4][4];
        ldsm4(a[0], vb + offA + ks * 32);
        ldsm4(a[1], vb + offA + 16 * 144 + ks * 32);
        #pragma unroll
        for (int p = 0; p < 4; ++p)
            ldsm4(bq[p], ab + offB + p * 16 * 144 + ks * 32);
        #pragma unroll
        for (int mt = 0; mt < 2; ++mt)
            #pragma unroll
            for (int p = 0; p < 4; ++p) {
                mma_f16(acc[mt][2 * p],     a[mt][0], a[mt][1], a[mt][2], a[mt][3],
                        bq[p][0], bq[p][2]);
                mma_f16(acc[mt][2 * p + 1], a[mt][0], a[mt][1], a[mt][2], a[mt][3],
                        bq[p][1], bq[p][3]);
            }
    }

    const int g = lane >> 2, t4 = lane & 3;
    #pragma unroll
    for (int mt = 0; mt < 2; ++mt) {
        #pragma unroll
        for (int nt = 0; nt < 8; ++nt) {
            const int n1 = n0 + w * 32 + mt * 16 + g;
            const int d  = nt * 8 + t4 * 2;
            __half* yp = h_attnout + ((size_t)(b * 4096 + n1)) * 256 + h * 64 + d;
            *(__half2*)yp = __floats2half2_rn(acc[mt][nt][0], acc[mt][nt][1]);
            *(__half2*)(yp + 8 * 256) = __floats2half2_rn(acc[mt][nt][2], acc[mt][nt][3]);
        }
    }
}

// ---------------- launch ----------------
extern "C" void kernel_launch(void* const* d_in, const int* in_sizes, int n_in,
                              void* d_out, int out_size)
{
    const float* x      = (const float*)d_in[0];
    const float* w_qkv  = (const float*)d_in[1];
    const float* b_qkv  = (const float*)d_in[2];
    const float* w_proj = (const float*)d_in[3];
    const float* b_proj = (const float*)d_in[4];
    const float* w_ffn1 = (const float*)d_in[5];
    const float* b_ffn1 = (const float*)d_in[6];
    const float* w_ffn2 = (const float*)d_in[7];
    const float* b_ffn2 = (const float*)d_in[8];
    const float* g1     = (const float*)d_in[9];
    const float* be1    = (const float*)d_in[10];
    const float* g2     = (const float*)d_in[11];
    const float* be2    = (const float*)d_in[12];
    float* out = (float*)d_out;

    void *p_xln, *p_v, *p_attnout, *p_ln2, *p_ffh, *p_w;
    cudaGetSymbolAddress(&p_xln, h_xln);
    cudaGetSymbolAddress(&p_v, h_v);
    cudaGetSymbolAddress(&p_attnout, h_attnout);
    cudaGetSymbolAddress(&p_ln2, h_ln2);
    cudaGetSymbolAddress(&p_ffh, h_ffh);
    cudaGetSymbolAddress(&p_w, h_w);
    const __half* hw = (const __half*)p_w;

    cudaFuncSetAttribute(gemm_h<0>, cudaFuncAttributeMaxDynamicSharedMemorySize, SMEM_DYN);
    cudaFuncSetAttribute(gemm_h<1>, cudaFuncAttributeMaxDynamicSharedMemorySize, SMEM_DYN);
    cudaFuncSetAttribute(gemm_h<2>, cudaFuncAttributeMaxDynamicSharedMemorySize, SMEM_DYN);
    cudaFuncSetAttribute(gemm_h<3>, cudaFuncAttributeMaxDynamicSharedMemorySize, SMEM_DYN);
    cudaFuncSetAttribute(gemm_h<4>, cudaFuncAttributeMaxDynamicSharedMemorySize, SMEM_DYN);

    static cudaStream_t s2 = [] { cudaStream_t s; cudaStreamCreateWithFlags(&s, cudaStreamNonBlocking); return s; }();
    static cudaEvent_t evA = [] { cudaEvent_t e; cudaEventCreateWithFlags(&e, cudaEventDisableTiming); return e; }();
    static cudaEvent_t evB = [] { cudaEvent_t e; cudaEventCreateWithFlags(&e, cudaEventDisableTiming); return e; }();
    static cudaEvent_t evC = [] { cudaEvent_t e; cudaEventCreateWithFlags(&e, cudaEventDisableTiming); return e; }();
    static cudaEvent_t evD = [] { cudaEvent_t e; cudaEventCreateWithFlags(&e, cudaEventDisableTiming); return e; }();
    static cudaEvent_t evG = [] { cudaEvent_t e; cudaEventCreateWithFlags(&e, cudaEventDisableTiming); return e; }();
    static cudaEvent_t evF = [] { cudaEvent_t e; cudaEventCreateWithFlags(&e, cudaEventDisableTiming); return e; }();

    const int M = kB * kN;    // 32768
    const int MT = M / 128;   // 256 m-tiles
    cudaStream_t s0 = 0;

    // fork: convw on s2, ln1 on s0
    cudaEventRecord(evA, s0);
    cudaStreamWaitEvent(s2, evA, 0);
    convw_kernel<<<(OW_TOT + 255) / 256, 256, 0, s2>>>(w_qkv, w_proj, w_ffn1, w_ffn2);
    cudaEventRecord(evB, s2);

    ln1_kernel<<<dim3(kN / 32, kB), 256, 0, s0>>>(x, g1, be1);

    // QKV q/k (needs ln1 + convw)
    cudaStreamWaitEvent(s0, evB, 0);
    gemm_h<3><<<dim3(4, MT), 256, SMEM_DYN, s0>>>(
        (const __half*)p_xln, hw + OW_QKV, b_qkv, nullptr, nullptr, nullptr, nullptr, kC, kC3, 0);
    cudaEventRecord(evC, s0);

    // QKV v on s2, concurrent with attn_s + softmax on s0
    cudaStreamWaitEvent(s2, evC, 0);
    gemm_h<0><<<dim3(2, MT), 256, SMEM_DYN, s2>>>(
        (const __half*)p_xln, hw + OW_QKV + 512 * kC, b_qkv + 512, p_v,
        nullptr, nullptr, nullptr, kC, kC, 0);
    cudaEventRecord(evD, s2);

    attn_s_tc<<<dim3(kBH, kNCH), 128, 0, s0>>>();
    softmax_kernel<<<dim3(kBH, 8), 256, 0, s0>>>();

    // AV half A (bh 0..15 => m-tiles 0..127); needs softmax (s0 order) + h_v (evD)
    cudaStreamWaitEvent(s0, evD, 0);
    attn_av_tc<<<dim3(kN / 128, kBH / 2), 128, 0, s0>>>(0);
    cudaEventRecord(evG, s0);

    // ---- pipeline A on s2: proj_A -> FFN1_A -> FFN2_A (m-tiles 0..127) ----
    cudaStreamWaitEvent(s2, evG, 0);
    gemm_h<4><<<dim3(1, MT / 2), 256, SMEM_DYN, s2>>>(
        (const __half*)p_attnout, hw + OW_PROJ, b_proj, p_ln2, nullptr, g2, be2, kC, kC, 0);
    gemm_h<1><<<dim3(kFFN / 128, MT / 2), 256, SMEM_DYN, s2>>>(
        (const __half*)p_ln2, hw + OW_FFN1, b_ffn1, p_ffh, nullptr, nullptr, nullptr, kC, kFFN, 0);
    gemm_h<2><<<dim3(kC / 128, MT / 2), 256, SMEM_DYN, s2>>>(
        (const __half*)p_ffh, hw + OW_FFN2, b_ffn2, out, x, nullptr, nullptr, kFFN, kC, 0);
    cudaEventRecord(evF, s2);

    // ---- pipeline B on s0: attn_av_B -> proj_B -> FFN1_B -> FFN2_B (m-tiles 128..255) ----
    attn_av_tc<<<dim3(kN / 128, kBH / 2), 128, 0, s0>>>(kBH / 2);
    gemm_h<4><<<dim3(1, MT / 2), 256, SMEM_DYN, s0>>>(
        (const __half*)p_attnout, hw + OW_PROJ, b_proj, p_ln2, nullptr, g2, be2, kC, kC, MT / 2);
    gemm_h<1><<<dim3(kFFN / 128, MT / 2), 256, SMEM_DYN, s0>>>(
        (const __half*)p_ln2, hw + OW_FFN1, b_ffn1, p_ffh, nullptr, nullptr, nullptr, kC, kFFN, MT / 2);
    gemm_h<2><<<dim3(kC / 128, MT / 2), 256, SMEM_DYN, s0>>>(
        (const __half*)p_ffh, hw + OW_FFN2, b_ffn2, out, x, nullptr, nullptr, kFFN, kC, MT / 2);

    // join pipeline A into s0
    cudaStreamWaitEvent(s0, evF, 0);
}